// round 1
// baseline (speedup 1.0000x reference)
#include <cuda_runtime.h>

#define NB 4
#define NN 2048
#define NE 256
#define NH 4
#define ND 64
#define NE2 512
#define NTOK 16384               // 2 * B * N
#define PER (NB*NH*NN*ND)        // 2,097,152 per (dir) qk/v buffer
#define QK_SCALE 0.35355339059327373f   // 64^-0.25

// ---------------- scratch (device globals; no allocation allowed) ----------
__device__ float g_qk[2][PER];               // [dir][B,H,N,D]
__device__ float g_v [2][PER];               // [dir][B,H,N,D]
__device__ float g_am[2][NB*NN*NE];          // attention out, merged heads [dir][B,N,E]
__device__ float g_cat[NTOK*NE2];            // [16384, 512]  (x | m@Wo+bo)
__device__ float g_h1 [NTOK*NE2];            // [16384, 512]  GEMM1 out, then LN+gelu in-place

// ---------------- generic 128x128x8 SGEMM, 8x8 per thread ------------------
// MODE 0: proj   A = x0|x1 [16384,256], W = Wqk|Wv -> g_qk (scaled) / g_v, head-major
// MODE 1: Wo     A = g_am  [16384,256], W = Wo     -> g_cat cols 256..511 (+bo)
// MODE 2: FFN1   A = g_cat [16384,512], W = W1     -> g_h1 (+b1)
// MODE 3: FFN2   A = g_h1  [16384,512], W = W2     -> d_out (+b2 + residual x)
template<int MODE>
__global__ void __launch_bounds__(256) sgemm_k(
    const float* __restrict__ Wa, const float* __restrict__ Wb,
    const float* __restrict__ ba, const float* __restrict__ bb,
    const float* __restrict__ r0, const float* __restrict__ r1,
    float* __restrict__ out, int K, int ldb)
{
    __shared__ float As[8][128];
    __shared__ float Bs[8][128];
    const int bx = blockIdx.x, by = blockIdx.y, tid = threadIdx.x;
    const int trow = tid >> 4, tcol = tid & 15;

    const float* Ab;
    const float* Bb;
    if constexpr (MODE == 0) {
        Ab = (by < 64) ? (r0 + (size_t)by * 128 * 256)
                       : (r1 + (size_t)(by - 64) * 128 * 256);
        int cb = bx * 128;
        Bb = (cb < 256) ? (Wa + cb) : (Wb + (cb - 256));
    } else {
        const float* Asrc = (MODE == 1) ? g_am[0] : ((MODE == 2) ? g_cat : g_h1);
        Ab = Asrc + (size_t)by * 128 * K;
        Bb = Wa + bx * 128;
    }

    const int aRow = tid >> 1, aCol = (tid & 1) * 4;
    const int bRow = tid >> 5, bCol = (tid & 31) * 4;

    float acc[8][8];
#pragma unroll
    for (int i = 0; i < 8; i++)
#pragma unroll
        for (int j = 0; j < 8; j++) acc[i][j] = 0.f;

    for (int k0 = 0; k0 < K; k0 += 8) {
        float4 a4 = *(const float4*)(Ab + (size_t)aRow * K + k0 + aCol);
        As[aCol + 0][aRow] = a4.x;
        As[aCol + 1][aRow] = a4.y;
        As[aCol + 2][aRow] = a4.z;
        As[aCol + 3][aRow] = a4.w;
        *(float4*)&Bs[bRow][bCol] =
            *(const float4*)(Bb + (size_t)(k0 + bRow) * ldb + bCol);
        __syncthreads();
#pragma unroll
        for (int kk = 0; kk < 8; kk++) {
            float af[8], bf[8];
            *(float4*)(af)     = *(float4*)&As[kk][trow * 8];
            *(float4*)(af + 4) = *(float4*)&As[kk][trow * 8 + 4];
            *(float4*)(bf)     = *(float4*)&Bs[kk][tcol * 8];
            *(float4*)(bf + 4) = *(float4*)&Bs[kk][tcol * 8 + 4];
#pragma unroll
            for (int i = 0; i < 8; i++)
#pragma unroll
                for (int j = 0; j < 8; j++)
                    acc[i][j] = fmaf(af[i], bf[j], acc[i][j]);
        }
        __syncthreads();
    }

#pragma unroll
    for (int i = 0; i < 8; i++) {
        int r = by * 128 + trow * 8 + i;
#pragma unroll
        for (int j = 0; j < 8; j++) {
            int c = bx * 128 + tcol * 8 + j;
            float v = acc[i][j];
            if constexpr (MODE == 0) {
                int src = r >> 13;
                int rl = r & 8191;
                int b = rl >> 11, n = rl & 2047;
                if (c < 256) {
                    int h = c >> 6, d = c & 63;
                    g_qk[src][(((size_t)(b * NH + h)) * NN + n) * ND + d] =
                        (v + ba[c]) * QK_SCALE;
                } else {
                    int c2 = c - 256;
                    int h = c2 >> 6, d = c2 & 63;
                    g_v[src][(((size_t)(b * NH + h)) * NN + n) * ND + d] = v + bb[c2];
                }
            } else if constexpr (MODE == 1) {
                g_cat[(size_t)r * NE2 + 256 + c] = v + ba[c];
            } else if constexpr (MODE == 2) {
                g_h1[(size_t)r * NE2 + c] = v + ba[c];
            } else {
                int src = r >> 13, rl = r & 8191;
                const float* xr = src ? r1 : r0;
                out[(size_t)r * NE + c] = v + ba[c] + xr[(size_t)rl * NE + c];
            }
        }
    }
}

// ---------------- flash attention, 64x64 tiles, fp32 -----------------------
// m0 = Attn(qk0, qk1, v1)  (dir=0),  m1 = Attn(qk1, qk0, v0)  (dir=1)
__global__ void __launch_bounds__(256) attn_kernel()
{
    extern __shared__ float sm[];
    float* Qs = sm;            // [64][64]
    float* Ks = sm + 4096;     // [64][65]  padded (kills 16-way conflicts)
    float* Vs = sm + 8256;     // [64][64]
    float* Ss = sm + 12352;    // [64][64]

    const int qt = blockIdx.x, bh = blockIdx.y, dir = blockIdx.z;
    const int tid = threadIdx.x;
    const int ty = tid >> 4, tx = tid & 15;

    const float* Q  = g_qk[dir]     + (size_t)bh * NN * ND + (size_t)qt * 64 * ND;
    const float* Kp = g_qk[dir ^ 1] + (size_t)bh * NN * ND;
    const float* Vp = g_v [dir ^ 1] + (size_t)bh * NN * ND;

#pragma unroll
    for (int i = 0; i < 4; i++) {
        int e = tid + i * 256;
        int r = e >> 4, c = (e & 15) * 4;
        float4 q4 = *(const float4*)(Q + r * ND + c);
        float* d = Qs + r * 64 + c;
        d[0] = q4.x; d[1] = q4.y; d[2] = q4.z; d[3] = q4.w;
    }

    float m_i[4], l_i[4], o[4][4];
#pragma unroll
    for (int i = 0; i < 4; i++) {
        m_i[i] = -1e30f; l_i[i] = 0.f;
#pragma unroll
        for (int j = 0; j < 4; j++) o[i][j] = 0.f;
    }
    __syncthreads();

    for (int j0 = 0; j0 < NN; j0 += 64) {
#pragma unroll
        for (int i = 0; i < 4; i++) {
            int e = tid + i * 256;
            int r = e >> 4, c = (e & 15) * 4;
            float4 k4 = *(const float4*)(Kp + (size_t)(j0 + r) * ND + c);
            float* dk = Ks + r * 65 + c;
            dk[0] = k4.x; dk[1] = k4.y; dk[2] = k4.z; dk[3] = k4.w;
            float4 v4 = *(const float4*)(Vp + (size_t)(j0 + r) * ND + c);
            float* dv = Vs + r * 64 + c;
            dv[0] = v4.x; dv[1] = v4.y; dv[2] = v4.z; dv[3] = v4.w;
        }
        __syncthreads();

        float s[4][4];
#pragma unroll
        for (int i = 0; i < 4; i++)
#pragma unroll
            for (int j = 0; j < 4; j++) s[i][j] = 0.f;
#pragma unroll 8
        for (int d = 0; d < 64; d++) {
            float qr[4], kr[4];
#pragma unroll
            for (int i = 0; i < 4; i++) qr[i] = Qs[(4 * ty + i) * 64 + d];
#pragma unroll
            for (int j = 0; j < 4; j++) kr[j] = Ks[(4 * tx + j) * 65 + d];
#pragma unroll
            for (int i = 0; i < 4; i++)
#pragma unroll
                for (int j = 0; j < 4; j++) s[i][j] = fmaf(qr[i], kr[j], s[i][j]);
        }

        // online softmax over the row dimension (16 tx-threads per row group)
#pragma unroll
        for (int i = 0; i < 4; i++) {
            float mx = fmaxf(fmaxf(s[i][0], s[i][1]), fmaxf(s[i][2], s[i][3]));
#pragma unroll
            for (int off = 8; off > 0; off >>= 1)
                mx = fmaxf(mx, __shfl_xor_sync(0xffffffffu, mx, off));
            float mn = fmaxf(m_i[i], mx);
            float corr = __expf(m_i[i] - mn);
            float ls = 0.f;
#pragma unroll
            for (int j = 0; j < 4; j++) {
                float p = __expf(s[i][j] - mn);
                s[i][j] = p;
                ls += p;
            }
#pragma unroll
            for (int off = 8; off > 0; off >>= 1)
                ls += __shfl_xor_sync(0xffffffffu, ls, off);
            l_i[i] = l_i[i] * corr + ls;
            m_i[i] = mn;
#pragma unroll
            for (int j = 0; j < 4; j++) o[i][j] *= corr;
#pragma unroll
            for (int j = 0; j < 4; j++) Ss[(4 * ty + i) * 64 + 4 * tx + j] = s[i][j];
        }
        __syncthreads();

#pragma unroll 8
        for (int kk = 0; kk < 64; kk++) {
            float pr[4], vr[4];
#pragma unroll
            for (int i = 0; i < 4; i++) pr[i] = Ss[(4 * ty + i) * 64 + kk];
#pragma unroll
            for (int j = 0; j < 4; j++) vr[j] = Vs[kk * 64 + 4 * tx + j];
#pragma unroll
            for (int i = 0; i < 4; i++)
#pragma unroll
                for (int j = 0; j < 4; j++) o[i][j] = fmaf(pr[i], vr[j], o[i][j]);
        }
        __syncthreads();
    }

    const int b = bh >> 2, h = bh & 3;
    float* amo = g_am[dir];
#pragma unroll
    for (int i = 0; i < 4; i++) {
        float inv = 1.f / l_i[i];
        int n = qt * 64 + 4 * ty + i;
#pragma unroll
        for (int j = 0; j < 4; j++)
            amo[((size_t)(b * NN + n)) * NE + h * ND + 4 * tx + j] = o[i][j] * inv;
    }
}

// ---------------- copy x into cat cols 0..255 ------------------------------
__global__ void copy_x_kernel(const float* __restrict__ x0, const float* __restrict__ x1)
{
    int idx = blockIdx.x * 256 + threadIdx.x;   // over 16384*64 float4s
    int r = idx >> 6;
    int c4 = (idx & 63) * 4;
    const float* x = (r < 8192) ? (x0 + (size_t)r * NE)
                                : (x1 + (size_t)(r - 8192) * NE);
    *(float4*)(g_cat + (size_t)r * NE2 + c4) = *(const float4*)(x + c4);
}

// ---------------- LayerNorm(512) + exact GELU, in-place on g_h1 ------------
__global__ void __launch_bounds__(128) ln_gelu_kernel(
    const float* __restrict__ gvec, const float* __restrict__ bvec)
{
    float* p = g_h1 + (size_t)blockIdx.x * NE2;
    int t = threadIdx.x;
    float4 v = ((const float4*)p)[t];
    float s = v.x + v.y + v.z + v.w;
    float q = v.x * v.x + v.y * v.y + v.z * v.z + v.w * v.w;
#pragma unroll
    for (int off = 16; off > 0; off >>= 1) {
        s += __shfl_xor_sync(0xffffffffu, s, off);
        q += __shfl_xor_sync(0xffffffffu, q, off);
    }
    __shared__ float rs_[4], rq_[4];
    if ((t & 31) == 0) { rs_[t >> 5] = s; rq_[t >> 5] = q; }
    __syncthreads();
    s = rs_[0] + rs_[1] + rs_[2] + rs_[3];
    q = rq_[0] + rq_[1] + rq_[2] + rq_[3];
    float mean = s * (1.f / 512.f);
    float var = q * (1.f / 512.f) - mean * mean;
    float r = rsqrtf(var + 1e-5f);
    float4 gv = ((const float4*)gvec)[t];
    float4 bv = ((const float4*)bvec)[t];
    float xn;
    xn = (v.x - mean) * r * gv.x + bv.x; v.x = 0.5f * xn * (1.f + erff(xn * 0.70710678118654752f));
    xn = (v.y - mean) * r * gv.y + bv.y; v.y = 0.5f * xn * (1.f + erff(xn * 0.70710678118654752f));
    xn = (v.z - mean) * r * gv.z + bv.z; v.z = 0.5f * xn * (1.f + erff(xn * 0.70710678118654752f));
    xn = (v.w - mean) * r * gv.w + bv.w; v.w = 0.5f * xn * (1.f + erff(xn * 0.70710678118654752f));
    ((float4*)p)[t] = v;
}

// ---------------------------------------------------------------------------
extern "C" void kernel_launch(void* const* d_in, const int* in_sizes, int n_in,
                              void* d_out, int out_size)
{
    const float* x0  = (const float*)d_in[0];
    const float* x1  = (const float*)d_in[1];
    const float* Wqk = (const float*)d_in[2];
    const float* bqk = (const float*)d_in[3];
    const float* Wv  = (const float*)d_in[4];
    const float* bv  = (const float*)d_in[5];
    const float* Wo  = (const float*)d_in[6];
    const float* bo  = (const float*)d_in[7];
    const float* W1  = (const float*)d_in[8];
    const float* b1  = (const float*)d_in[9];
    const float* lng = (const float*)d_in[10];
    const float* lnb = (const float*)d_in[11];
    const float* W2  = (const float*)d_in[12];
    const float* b2  = (const float*)d_in[13];
    float* out = (float*)d_out;

    (void)in_sizes; (void)n_in; (void)out_size;

    cudaFuncSetAttribute(attn_kernel,
                         cudaFuncAttributeMaxDynamicSharedMemorySize, 65792);

    // 1) fused qk/v projection (both inputs, both weight mats)
    sgemm_k<0><<<dim3(4, 128), 256>>>(Wqk, Wv, bqk, bv, x0, x1, nullptr, 256, 256);
    // 2) bidirectional flash attention
    attn_kernel<<<dim3(32, 16, 2), 256, 65792>>>();
    // 3) x -> cat cols [0,256)
    copy_x_kernel<<<4096, 256>>>(x0, x1);
    // 4) Wo projection -> cat cols [256,512)
    sgemm_k<1><<<dim3(2, 128), 256>>>(Wo, nullptr, bo, nullptr, nullptr, nullptr, nullptr, 256, 256);
    // 5) FFN GEMM1
    sgemm_k<2><<<dim3(4, 128), 256>>>(W1, nullptr, b1, nullptr, nullptr, nullptr, nullptr, 512, 512);
    // 6) LayerNorm + GELU (in place)
    ln_gelu_kernel<<<16384, 128>>>(lng, lnb);
    // 7) FFN GEMM2 + bias + residual -> d_out
    sgemm_k<3><<<dim3(2, 128), 256>>>(W2, nullptr, b2, nullptr, x0, x1, out, 512, 256);
}

// round 2
// speedup vs baseline: 1.0008x; 1.0008x over previous
#include <cuda_runtime.h>

#define NB 4
#define NN 2048
#define NE 256
#define NH 4
#define ND 64
#define NE2 512
#define NTOK 16384               // 2 * B * N
#define PER (NB*NH*NN*ND)        // 2,097,152 per (dir) qk/v buffer
#define QK_SCALE 0.35355339059327373f   // 64^-0.25

// ---------------- scratch (device globals; no allocation allowed) ----------
__device__ float g_qk[2][PER];               // [dir][B,H,N,D]
__device__ float g_v [2][PER];               // [dir][B,H,N,D]
__device__ float g_am[2][NB*NN*NE];          // attention out, merged heads [dir][B,N,E]
__device__ float g_cat[NTOK*NE2];            // [16384, 512]  (x | m@Wo+bo)
__device__ float g_h1 [NTOK*NE2];            // [16384, 512]  GEMM1 out, then LN+gelu in-place

// ---------------- generic 128x128x8 SGEMM, 8x8 per thread ------------------
// MODE 0: proj   A = x0|x1 [16384,256], W = Wqk|Wv -> g_qk (scaled) / g_v, head-major
// MODE 1: Wo     A = g_am  [16384,256], W = Wo     -> g_cat cols 256..511 (+bo)
// MODE 2: FFN1   A = g_cat [16384,512], W = W1     -> g_h1 (+b1)
// MODE 3: FFN2   A = g_h1  [16384,512], W = W2     -> d_out (+b2 + residual x)
template<int MODE>
__global__ void __launch_bounds__(256) sgemm_k(
    const float* __restrict__ Wa, const float* __restrict__ Wb,
    const float* __restrict__ ba, const float* __restrict__ bb,
    const float* __restrict__ r0, const float* __restrict__ r1,
    float* __restrict__ out, int K, int ldb)
{
    __shared__ float As[8][128];
    __shared__ float Bs[8][128];
    const int bx = blockIdx.x, by = blockIdx.y, tid = threadIdx.x;
    const int trow = tid >> 4, tcol = tid & 15;

    const float* Ab;
    const float* Bb;
    if constexpr (MODE == 0) {
        Ab = (by < 64) ? (r0 + (size_t)by * 128 * 256)
                       : (r1 + (size_t)(by - 64) * 128 * 256);
        int cb = bx * 128;
        Bb = (cb < 256) ? (Wa + cb) : (Wb + (cb - 256));
    } else {
        const float* Asrc = (MODE == 1) ? g_am[0] : ((MODE == 2) ? g_cat : g_h1);
        Ab = Asrc + (size_t)by * 128 * K;
        Bb = Wa + bx * 128;
    }

    const int aRow = tid >> 1, aCol = (tid & 1) * 4;
    const int bRow = tid >> 5, bCol = (tid & 31) * 4;

    float acc[8][8];
#pragma unroll
    for (int i = 0; i < 8; i++)
#pragma unroll
        for (int j = 0; j < 8; j++) acc[i][j] = 0.f;

    for (int k0 = 0; k0 < K; k0 += 8) {
        float4 a4 = *(const float4*)(Ab + (size_t)aRow * K + k0 + aCol);
        As[aCol + 0][aRow] = a4.x;
        As[aCol + 1][aRow] = a4.y;
        As[aCol + 2][aRow] = a4.z;
        As[aCol + 3][aRow] = a4.w;
        *(float4*)&Bs[bRow][bCol] =
            *(const float4*)(Bb + (size_t)(k0 + bRow) * ldb + bCol);
        __syncthreads();
#pragma unroll
        for (int kk = 0; kk < 8; kk++) {
            float af[8], bf[8];
            *(float4*)(af)     = *(float4*)&As[kk][trow * 8];
            *(float4*)(af + 4) = *(float4*)&As[kk][trow * 8 + 4];
            *(float4*)(bf)     = *(float4*)&Bs[kk][tcol * 8];
            *(float4*)(bf + 4) = *(float4*)&Bs[kk][tcol * 8 + 4];
#pragma unroll
            for (int i = 0; i < 8; i++)
#pragma unroll
                for (int j = 0; j < 8; j++)
                    acc[i][j] = fmaf(af[i], bf[j], acc[i][j]);
        }
        __syncthreads();
    }

#pragma unroll
    for (int i = 0; i < 8; i++) {
        int r = by * 128 + trow * 8 + i;
#pragma unroll
        for (int j = 0; j < 8; j++) {
            int c = bx * 128 + tcol * 8 + j;
            float v = acc[i][j];
            if constexpr (MODE == 0) {
                int src = r >> 13;
                int rl = r & 8191;
                int b = rl >> 11, n = rl & 2047;
                if (c < 256) {
                    int h = c >> 6, d = c & 63;
                    g_qk[src][(((size_t)(b * NH + h)) * NN + n) * ND + d] =
                        (v + ba[c]) * QK_SCALE;
                } else {
                    int c2 = c - 256;
                    int h = c2 >> 6, d = c2 & 63;
                    g_v[src][(((size_t)(b * NH + h)) * NN + n) * ND + d] = v + bb[c2];
                }
            } else if constexpr (MODE == 1) {
                g_cat[(size_t)r * NE2 + 256 + c] = v + ba[c];
            } else if constexpr (MODE == 2) {
                g_h1[(size_t)r * NE2 + c] = v + ba[c];
            } else {
                int src = r >> 13, rl = r & 8191;
                const float* xr = src ? r1 : r0;
                out[(size_t)r * NE + c] = v + ba[c] + xr[(size_t)rl * NE + c];
            }
        }
    }
}

// ---------------- flash attention, 64x64 tiles, fp32 -----------------------
// m0 = Attn(qk0, qk1, v1)  (dir=0),  m1 = Attn(qk1, qk0, v0)  (dir=1)
__global__ void __launch_bounds__(256) attn_kernel()
{
    extern __shared__ float sm[];
    float* Qs = sm;            // [64][64]
    float* Ks = sm + 4096;     // [64][65]  padded (kills 16-way conflicts)
    float* Vs = sm + 8256;     // [64][64]
    float* Ss = sm + 12352;    // [64][64]

    const int qt = blockIdx.x, bh = blockIdx.y, dir = blockIdx.z;
    const int tid = threadIdx.x;
    const int ty = tid >> 4, tx = tid & 15;

    const float* Q  = g_qk[dir]     + (size_t)bh * NN * ND + (size_t)qt * 64 * ND;
    const float* Kp = g_qk[dir ^ 1] + (size_t)bh * NN * ND;
    const float* Vp = g_v [dir ^ 1] + (size_t)bh * NN * ND;

#pragma unroll
    for (int i = 0; i < 4; i++) {
        int e = tid + i * 256;
        int r = e >> 4, c = (e & 15) * 4;
        float4 q4 = *(const float4*)(Q + r * ND + c);
        float* d = Qs + r * 64 + c;
        d[0] = q4.x; d[1] = q4.y; d[2] = q4.z; d[3] = q4.w;
    }

    float m_i[4], l_i[4], o[4][4];
#pragma unroll
    for (int i = 0; i < 4; i++) {
        m_i[i] = -1e30f; l_i[i] = 0.f;
#pragma unroll
        for (int j = 0; j < 4; j++) o[i][j] = 0.f;
    }
    __syncthreads();

    for (int j0 = 0; j0 < NN; j0 += 64) {
#pragma unroll
        for (int i = 0; i < 4; i++) {
            int e = tid + i * 256;
            int r = e >> 4, c = (e & 15) * 4;
            float4 k4 = *(const float4*)(Kp + (size_t)(j0 + r) * ND + c);
            float* dk = Ks + r * 65 + c;
            dk[0] = k4.x; dk[1] = k4.y; dk[2] = k4.z; dk[3] = k4.w;
            float4 v4 = *(const float4*)(Vp + (size_t)(j0 + r) * ND + c);
            float* dv = Vs + r * 64 + c;
            dv[0] = v4.x; dv[1] = v4.y; dv[2] = v4.z; dv[3] = v4.w;
        }
        __syncthreads();

        float s[4][4];
#pragma unroll
        for (int i = 0; i < 4; i++)
#pragma unroll
            for (int j = 0; j < 4; j++) s[i][j] = 0.f;
#pragma unroll 8
        for (int d = 0; d < 64; d++) {
            float qr[4], kr[4];
#pragma unroll
            for (int i = 0; i < 4; i++) qr[i] = Qs[(4 * ty + i) * 64 + d];
#pragma unroll
            for (int j = 0; j < 4; j++) kr[j] = Ks[(4 * tx + j) * 65 + d];
#pragma unroll
            for (int i = 0; i < 4; i++)
#pragma unroll
                for (int j = 0; j < 4; j++) s[i][j] = fmaf(qr[i], kr[j], s[i][j]);
        }

        // online softmax over the row dimension (16 tx-threads per row group)
#pragma unroll
        for (int i = 0; i < 4; i++) {
            float mx = fmaxf(fmaxf(s[i][0], s[i][1]), fmaxf(s[i][2], s[i][3]));
#pragma unroll
            for (int off = 8; off > 0; off >>= 1)
                mx = fmaxf(mx, __shfl_xor_sync(0xffffffffu, mx, off));
            float mn = fmaxf(m_i[i], mx);
            float corr = __expf(m_i[i] - mn);
            float ls = 0.f;
#pragma unroll
            for (int j = 0; j < 4; j++) {
                float p = __expf(s[i][j] - mn);
                s[i][j] = p;
                ls += p;
            }
#pragma unroll
            for (int off = 8; off > 0; off >>= 1)
                ls += __shfl_xor_sync(0xffffffffu, ls, off);
            l_i[i] = l_i[i] * corr + ls;
            m_i[i] = mn;
#pragma unroll
            for (int j = 0; j < 4; j++) o[i][j] *= corr;
#pragma unroll
            for (int j = 0; j < 4; j++) Ss[(4 * ty + i) * 64 + 4 * tx + j] = s[i][j];
        }
        __syncthreads();

#pragma unroll 8
        for (int kk = 0; kk < 64; kk++) {
            float pr[4], vr[4];
#pragma unroll
            for (int i = 0; i < 4; i++) pr[i] = Ss[(4 * ty + i) * 64 + kk];
#pragma unroll
            for (int j = 0; j < 4; j++) vr[j] = Vs[kk * 64 + 4 * tx + j];
#pragma unroll
            for (int i = 0; i < 4; i++)
#pragma unroll
                for (int j = 0; j < 4; j++) o[i][j] = fmaf(pr[i], vr[j], o[i][j]);
        }
        __syncthreads();
    }

    const int b = bh >> 2, h = bh & 3;
    float* amo = g_am[dir];
#pragma unroll
    for (int i = 0; i < 4; i++) {
        float inv = 1.f / l_i[i];
        int n = qt * 64 + 4 * ty + i;
#pragma unroll
        for (int j = 0; j < 4; j++)
            amo[((size_t)(b * NN + n)) * NE + h * ND + 4 * tx + j] = o[i][j] * inv;
    }
}

// ---------------- copy x into cat cols 0..255 ------------------------------
__global__ void copy_x_kernel(const float* __restrict__ x0, const float* __restrict__ x1)
{
    int idx = blockIdx.x * 256 + threadIdx.x;   // over 16384*64 float4s
    int r = idx >> 6;
    int c4 = (idx & 63) * 4;
    const float* x = (r < 8192) ? (x0 + (size_t)r * NE)
                                : (x1 + (size_t)(r - 8192) * NE);
    *(float4*)(g_cat + (size_t)r * NE2 + c4) = *(const float4*)(x + c4);
}

// ---------------- LayerNorm(512) + exact GELU, in-place on g_h1 ------------
__global__ void __launch_bounds__(128) ln_gelu_kernel(
    const float* __restrict__ gvec, const float* __restrict__ bvec)
{
    float* p = g_h1 + (size_t)blockIdx.x * NE2;
    int t = threadIdx.x;
    float4 v = ((const float4*)p)[t];
    float s = v.x + v.y + v.z + v.w;
    float q = v.x * v.x + v.y * v.y + v.z * v.z + v.w * v.w;
#pragma unroll
    for (int off = 16; off > 0; off >>= 1) {
        s += __shfl_xor_sync(0xffffffffu, s, off);
        q += __shfl_xor_sync(0xffffffffu, q, off);
    }
    __shared__ float rs_[4], rq_[4];
    if ((t & 31) == 0) { rs_[t >> 5] = s; rq_[t >> 5] = q; }
    __syncthreads();
    s = rs_[0] + rs_[1] + rs_[2] + rs_[3];
    q = rq_[0] + rq_[1] + rq_[2] + rq_[3];
    float mean = s * (1.f / 512.f);
    float var = q * (1.f / 512.f) - mean * mean;
    float r = rsqrtf(var + 1e-5f);
    float4 gv = ((const float4*)gvec)[t];
    float4 bv = ((const float4*)bvec)[t];
    float xn;
    xn = (v.x - mean) * r * gv.x + bv.x; v.x = 0.5f * xn * (1.f + erff(xn * 0.70710678118654752f));
    xn = (v.y - mean) * r * gv.y + bv.y; v.y = 0.5f * xn * (1.f + erff(xn * 0.70710678118654752f));
    xn = (v.z - mean) * r * gv.z + bv.z; v.z = 0.5f * xn * (1.f + erff(xn * 0.70710678118654752f));
    xn = (v.w - mean) * r * gv.w + bv.w; v.w = 0.5f * xn * (1.f + erff(xn * 0.70710678118654752f));
    ((float4*)p)[t] = v;
}

// ---------------------------------------------------------------------------
extern "C" void kernel_launch(void* const* d_in, const int* in_sizes, int n_in,
                              void* d_out, int out_size)
{
    const float* x0  = (const float*)d_in[0];
    const float* x1  = (const float*)d_in[1];
    const float* Wqk = (const float*)d_in[2];
    const float* bqk = (const float*)d_in[3];
    const float* Wv  = (const float*)d_in[4];
    const float* bv  = (const float*)d_in[5];
    const float* Wo  = (const float*)d_in[6];
    const float* bo  = (const float*)d_in[7];
    const float* W1  = (const float*)d_in[8];
    const float* b1  = (const float*)d_in[9];
    const float* lng = (const float*)d_in[10];
    const float* lnb = (const float*)d_in[11];
    const float* W2  = (const float*)d_in[12];
    const float* b2  = (const float*)d_in[13];
    float* out = (float*)d_out;

    (void)in_sizes; (void)n_in; (void)out_size;

    cudaFuncSetAttribute(attn_kernel,
                         cudaFuncAttributeMaxDynamicSharedMemorySize, 65792);

    // 1) fused qk/v projection (both inputs, both weight mats)
    sgemm_k<0><<<dim3(4, 128), 256>>>(Wqk, Wv, bqk, bv, x0, x1, nullptr, 256, 256);
    // 2) bidirectional flash attention
    attn_kernel<<<dim3(32, 16, 2), 256, 65792>>>();
    // 3) x -> cat cols [0,256)
    copy_x_kernel<<<4096, 256>>>(x0, x1);
    // 4) Wo projection -> cat cols [256,512)
    sgemm_k<1><<<dim3(2, 128), 256>>>(Wo, nullptr, bo, nullptr, nullptr, nullptr, nullptr, 256, 256);
    // 5) FFN GEMM1
    sgemm_k<2><<<dim3(4, 128), 256>>>(W1, nullptr, b1, nullptr, nullptr, nullptr, nullptr, 512, 512);
    // 6) LayerNorm + GELU (in place)
    ln_gelu_kernel<<<16384, 128>>>(lng, lnb);
    // 7) FFN GEMM2 + bias + residual -> d_out
    sgemm_k<3><<<dim3(2, 128), 256>>>(W2, nullptr, b2, nullptr, x0, x1, out, 512, 256);
}

// round 3
// speedup vs baseline: 2.7458x; 2.7436x over previous
#include <cuda_runtime.h>
#include <cstdint>

#define NB 4
#define NN 2048
#define NE 256
#define NH 4
#define ND 64
#define NE2 512
#define NTOK 16384               // 2 * B * N
#define PER (NB*NH*NN*ND)        // per-dir qk/v buffer
#define QK_SCALE 0.35355339059327373f   // 64^-0.25

// ---------------- scratch (device globals; no allocation allowed) ----------
__device__ float g_qk[2][PER];               // [dir][B,H,N,D]
__device__ float g_v [2][PER];               // [dir][B,H,N,D]
__device__ float g_am[2][NB*NN*NE];          // attention out, merged heads [dir][B,N,E]
__device__ float g_cat[NTOK*NE2];            // [16384, 512]  (x | m@Wo+bo)
__device__ float g_h1 [NTOK*NE2];            // [16384, 512]

// ---------------- tf32 mma helpers -----------------------------------------
__device__ __forceinline__ uint32_t f2tf(float x) {
    uint32_t r;
    asm("cvt.rna.tf32.f32 %0, %1;" : "=r"(r) : "f"(x));
    return r;
}
__device__ __forceinline__ void st4tf(uint32_t* dst, float4 v) {
    uint4 u;
    u.x = f2tf(v.x); u.y = f2tf(v.y); u.z = f2tf(v.z); u.w = f2tf(v.w);
    *(uint4*)dst = u;
}
__device__ __forceinline__ void mma8(float* d, const uint32_t* a, const uint32_t* b) {
    asm volatile(
        "mma.sync.aligned.m16n8k8.row.col.f32.tf32.tf32.f32 "
        "{%0,%1,%2,%3}, {%4,%5,%6,%7}, {%8,%9}, {%0,%1,%2,%3};\n"
        : "+f"(d[0]), "+f"(d[1]), "+f"(d[2]), "+f"(d[3])
        : "r"(a[0]), "r"(a[1]), "r"(a[2]), "r"(a[3]), "r"(b[0]), "r"(b[1]));
}

// ---------------- tf32 tensor-core GEMM, 128x128 block, 8 warps ------------
// warp tile 32x64 (2 m-tiles x 8 n-tiles of m16n8k8), K-tile 32
// MODE 0: proj   A = x0|x1 [16384,256], W = Wqk|Wv -> g_qk (scaled) / g_v
// MODE 1: Wo     A = g_am  [16384,256], W = Wo     -> g_cat cols 256..511 (+bo)
// MODE 2: FFN1   A = g_cat [16384,512], W = W1     -> g_h1 (+b1)
// MODE 3: FFN2   A = g_h1  [16384,512], W = W2     -> d_out (+b2 + residual)
template<int MODE>
__global__ void __launch_bounds__(256, 2) mgemm(
    const float* __restrict__ Wa, const float* __restrict__ Wb,
    const float* __restrict__ ba, const float* __restrict__ bb,
    const float* __restrict__ r0, const float* __restrict__ r1,
    float* __restrict__ out, int K, int ldb)
{
    __shared__ uint32_t As[128][36];   // [m][k], pad 36: frag banks 4g+t (CF)
    __shared__ uint32_t Bs[32][136];   // [k][n], pad 136: frag banks 8t+g (CF)

    const int tid = threadIdx.x, wid = tid >> 5, lane = tid & 31;
    const int wm = wid & 3, wn = wid >> 2;       // 4 x 2 warp grid
    const int g = lane >> 2, t = lane & 3;
    const int bx = blockIdx.x, by = blockIdx.y;

    const float* Ab;
    const float* Bb;
    if constexpr (MODE == 0) {
        Ab = (by < 64) ? (r0 + (size_t)by * 128 * 256)
                       : (r1 + (size_t)(by - 64) * 128 * 256);
        int cb = bx * 128;
        Bb = (cb < 256) ? (Wa + cb) : (Wb + (cb - 256));
    } else {
        const float* Asrc = (MODE == 1) ? g_am[0] : ((MODE == 2) ? g_cat : g_h1);
        Ab = Asrc + (size_t)by * 128 * K;
        Bb = Wa + bx * 128;
    }

    float acc[2][8][4];
#pragma unroll
    for (int i = 0; i < 2; i++)
#pragma unroll
        for (int j = 0; j < 8; j++)
#pragma unroll
            for (int c = 0; c < 4; c++) acc[i][j][c] = 0.f;

    const int arow = tid >> 3, ak = (tid & 7) * 4;       // A: 32 rows/pass
    const int brow = tid >> 3, bc = (tid & 7) * 16;      // B: each thread 16 cols

    for (int k0 = 0; k0 < K; k0 += 32) {
#pragma unroll
        for (int i = 0; i < 4; i++) {
            int m = i * 32 + arow;
            st4tf(&As[m][ak], *(const float4*)(Ab + (size_t)m * K + k0 + ak));
        }
#pragma unroll
        for (int j = 0; j < 4; j++) {
            st4tf(&Bs[brow][bc + 4 * j],
                  *(const float4*)(Bb + (size_t)(k0 + brow) * ldb + bc + 4 * j));
        }
        __syncthreads();

#pragma unroll
        for (int ks = 0; ks < 32; ks += 8) {
            uint32_t af[2][4], bf[8][2];
#pragma unroll
            for (int mt = 0; mt < 2; mt++) {
                int mr = wm * 32 + mt * 16 + g;
                af[mt][0] = As[mr][ks + t];
                af[mt][1] = As[mr + 8][ks + t];
                af[mt][2] = As[mr][ks + t + 4];
                af[mt][3] = As[mr + 8][ks + t + 4];
            }
#pragma unroll
            for (int nt = 0; nt < 8; nt++) {
                int nc = wn * 64 + nt * 8 + g;
                bf[nt][0] = Bs[ks + t][nc];
                bf[nt][1] = Bs[ks + t + 4][nc];
            }
#pragma unroll
            for (int mt = 0; mt < 2; mt++)
#pragma unroll
                for (int nt = 0; nt < 8; nt++)
                    mma8(acc[mt][nt], af[mt], bf[nt]);
        }
        __syncthreads();
    }

    // epilogue: c0,c1 -> row g cols 2t,2t+1 ; c2,c3 -> row g+8
#pragma unroll
    for (int mt = 0; mt < 2; mt++)
#pragma unroll
    for (int h = 0; h < 2; h++) {
        int r = by * 128 + wm * 32 + mt * 16 + g + h * 8;
#pragma unroll
        for (int nt = 0; nt < 8; nt++) {
            int c = bx * 128 + wn * 64 + nt * 8 + 2 * t;
            float v0 = acc[mt][nt][h * 2 + 0];
            float v1 = acc[mt][nt][h * 2 + 1];
            if constexpr (MODE == 0) {
                int src = r >> 13, rl = r & 8191;
                int b = rl >> 11, n = rl & 2047;
                if (c < 256) {
                    float2 bb2 = *(const float2*)&ba[c];
                    int hh = c >> 6, d = c & 63;
                    float2 w;
                    w.x = (v0 + bb2.x) * QK_SCALE;
                    w.y = (v1 + bb2.y) * QK_SCALE;
                    *(float2*)&g_qk[src][(((size_t)(b * NH + hh)) * NN + n) * ND + d] = w;
                } else {
                    int c2 = c - 256;
                    float2 bb2 = *(const float2*)&bb[c2];
                    int hh = c2 >> 6, d = c2 & 63;
                    float2 w; w.x = v0 + bb2.x; w.y = v1 + bb2.y;
                    *(float2*)&g_v[src][(((size_t)(b * NH + hh)) * NN + n) * ND + d] = w;
                }
            } else if constexpr (MODE == 1) {
                float2 bb2 = *(const float2*)&ba[c];
                float2 w; w.x = v0 + bb2.x; w.y = v1 + bb2.y;
                *(float2*)&g_cat[(size_t)r * NE2 + 256 + c] = w;
            } else if constexpr (MODE == 2) {
                float2 bb2 = *(const float2*)&ba[c];
                float2 w; w.x = v0 + bb2.x; w.y = v1 + bb2.y;
                *(float2*)&g_h1[(size_t)r * NE2 + c] = w;
            } else {
                int src = r >> 13, rl = r & 8191;
                const float* xr = src ? r1 : r0;
                float2 bb2 = *(const float2*)&ba[c];
                float2 xv = *(const float2*)&xr[(size_t)rl * NE + c];
                float2 w; w.x = v0 + bb2.x + xv.x; w.y = v1 + bb2.y + xv.y;
                *(float2*)&out[(size_t)r * NE + c] = w;
            }
        }
    }
}

// ---------------- flash attention, tf32 mma, 256-row Q tiles ---------------
// each warp owns 32 q rows (full n=64 per row -> softmax stays in-warp)
__global__ void __launch_bounds__(256, 1) attn_mma()
{
    extern __shared__ uint32_t smx[];
    uint32_t (*Qs)[68] = (uint32_t(*)[68])(smx);           // 256 x 68
    uint32_t (*Ks)[68] = (uint32_t(*)[68])(smx + 17408);   //  64 x 68
    uint32_t (*Vs)[68] = (uint32_t(*)[68])(smx + 21760);   //  64 x 68
    uint32_t (*Ps)[68] = (uint32_t(*)[68])(smx + 26112);   // 256 x 68

    const int qt = blockIdx.x, bh = blockIdx.y, dir = blockIdx.z;
    const int tid = threadIdx.x, wid = tid >> 5, lane = tid & 31;
    const int g = lane >> 2, t = lane & 3;
    const int mq = wid * 32;

    const float* Q  = g_qk[dir]     + (size_t)bh * NN * ND + (size_t)qt * 256 * ND;
    const float* Kp = g_qk[dir ^ 1] + (size_t)bh * NN * ND;
    const float* Vp = g_v [dir ^ 1] + (size_t)bh * NN * ND;

    {
        int rr = tid >> 3, cc = (tid & 7) * 8;
#pragma unroll
        for (int i = 0; i < 8; i++) {
            int row = i * 32 + rr;
            const float* src = Q + (size_t)row * ND + cc;
            st4tf(&Qs[row][cc], *(const float4*)src);
            st4tf(&Qs[row][cc + 4], *(const float4*)(src + 4));
        }
    }

    float o[2][8][4];
    float m_s[4], l_s[4];
#pragma unroll
    for (int i = 0; i < 4; i++) { m_s[i] = -1e30f; l_s[i] = 0.f; }
#pragma unroll
    for (int mt = 0; mt < 2; mt++)
#pragma unroll
        for (int nt = 0; nt < 8; nt++)
#pragma unroll
            for (int c = 0; c < 4; c++) o[mt][nt][c] = 0.f;
    __syncthreads();

    const int krr = tid >> 2, kcc = (tid & 3) * 16;

    for (int j0 = 0; j0 < NN; j0 += 64) {
        const float* ksrc = Kp + (size_t)(j0 + krr) * ND + kcc;
        const float* vsrc = Vp + (size_t)(j0 + krr) * ND + kcc;
#pragma unroll
        for (int j = 0; j < 4; j++) {
            st4tf(&Ks[krr][kcc + 4 * j], *(const float4*)(ksrc + 4 * j));
            st4tf(&Vs[krr][kcc + 4 * j], *(const float4*)(vsrc + 4 * j));
        }
        __syncthreads();

        // S = Q K^T  (32 x 64 per warp)
        float s[2][8][4];
#pragma unroll
        for (int mt = 0; mt < 2; mt++)
#pragma unroll
            for (int nt = 0; nt < 8; nt++)
#pragma unroll
                for (int c = 0; c < 4; c++) s[mt][nt][c] = 0.f;

#pragma unroll
        for (int ks = 0; ks < 64; ks += 8) {
            uint32_t af[2][4], bf[8][2];
#pragma unroll
            for (int mt = 0; mt < 2; mt++) {
                int mr = mq + mt * 16 + g;
                af[mt][0] = Qs[mr][ks + t];
                af[mt][1] = Qs[mr + 8][ks + t];
                af[mt][2] = Qs[mr][ks + t + 4];
                af[mt][3] = Qs[mr + 8][ks + t + 4];
            }
#pragma unroll
            for (int nt = 0; nt < 8; nt++) {
                bf[nt][0] = Ks[nt * 8 + g][ks + t];
                bf[nt][1] = Ks[nt * 8 + g][ks + t + 4];
            }
#pragma unroll
            for (int mt = 0; mt < 2; mt++)
#pragma unroll
                for (int nt = 0; nt < 8; nt++)
                    mma8(s[mt][nt], af[mt], bf[nt]);
        }

        // online softmax, per owned row (rows g / g+8 per m-tile)
#pragma unroll
        for (int mt = 0; mt < 2; mt++)
#pragma unroll
        for (int h = 0; h < 2; h++) {
            const int si = mt * 2 + h;
            float mx = -1e30f;
#pragma unroll
            for (int nt = 0; nt < 8; nt++)
                mx = fmaxf(mx, fmaxf(s[mt][nt][2 * h], s[mt][nt][2 * h + 1]));
            mx = fmaxf(mx, __shfl_xor_sync(0xffffffffu, mx, 1));
            mx = fmaxf(mx, __shfl_xor_sync(0xffffffffu, mx, 2));
            float mn = fmaxf(m_s[si], mx);
            float corr = __expf(m_s[si] - mn);
            m_s[si] = mn;
            float ls = 0.f;
            const int prow = mq + mt * 16 + g + h * 8;
#pragma unroll
            for (int nt = 0; nt < 8; nt++) {
                float p0 = __expf(s[mt][nt][2 * h] - mn);
                float p1 = __expf(s[mt][nt][2 * h + 1] - mn);
                ls += p0 + p1;
                uint2 pv;
                pv.x = __float_as_uint(p0);
                pv.y = __float_as_uint(p1);
                *(uint2*)&Ps[prow][nt * 8 + 2 * t] = pv;
            }
            ls += __shfl_xor_sync(0xffffffffu, ls, 1);
            ls += __shfl_xor_sync(0xffffffffu, ls, 2);
            l_s[si] = l_s[si] * corr + ls;
#pragma unroll
            for (int nt = 0; nt < 8; nt++) {
                o[mt][nt][2 * h] *= corr;
                o[mt][nt][2 * h + 1] *= corr;
            }
        }
        __syncwarp();

        // O += P V
#pragma unroll
        for (int ks = 0; ks < 64; ks += 8) {
            uint32_t af[2][4], bf[8][2];
#pragma unroll
            for (int mt = 0; mt < 2; mt++) {
                int mr = mq + mt * 16 + g;
                af[mt][0] = Ps[mr][ks + t];
                af[mt][1] = Ps[mr + 8][ks + t];
                af[mt][2] = Ps[mr][ks + t + 4];
                af[mt][3] = Ps[mr + 8][ks + t + 4];
            }
#pragma unroll
            for (int nt = 0; nt < 8; nt++) {
                bf[nt][0] = Vs[ks + t][nt * 8 + g];
                bf[nt][1] = Vs[ks + t + 4][nt * 8 + g];
            }
#pragma unroll
            for (int mt = 0; mt < 2; mt++)
#pragma unroll
                for (int nt = 0; nt < 8; nt++)
                    mma8(o[mt][nt], af[mt], bf[nt]);
        }
        __syncthreads();
    }

    const int b = bh >> 2, hd = bh & 3;
    float* amo = g_am[dir];
#pragma unroll
    for (int mt = 0; mt < 2; mt++)
#pragma unroll
    for (int h = 0; h < 2; h++) {
        const int si = mt * 2 + h;
        float inv = 1.f / l_s[si];
        int n = qt * 256 + mq + mt * 16 + g + h * 8;
        size_t base = ((size_t)(b * NN + n)) * NE + hd * ND;
#pragma unroll
        for (int nt = 0; nt < 8; nt++) {
            float2 w;
            w.x = o[mt][nt][2 * h] * inv;
            w.y = o[mt][nt][2 * h + 1] * inv;
            *(float2*)&amo[base + nt * 8 + 2 * t] = w;
        }
    }
}

// ---------------- copy x into cat cols 0..255 ------------------------------
__global__ void copy_x_kernel(const float* __restrict__ x0, const float* __restrict__ x1)
{
    int idx = blockIdx.x * 256 + threadIdx.x;   // over 16384*64 float4s
    int r = idx >> 6;
    int c4 = (idx & 63) * 4;
    const float* x = (r < 8192) ? (x0 + (size_t)r * NE)
                                : (x1 + (size_t)(r - 8192) * NE);
    *(float4*)(g_cat + (size_t)r * NE2 + c4) = *(const float4*)(x + c4);
}

// ---------------- LayerNorm(512) + exact GELU, in-place on g_h1 ------------
__global__ void __launch_bounds__(128) ln_gelu_kernel(
    const float* __restrict__ gvec, const float* __restrict__ bvec)
{
    float* p = g_h1 + (size_t)blockIdx.x * NE2;
    int t = threadIdx.x;
    float4 v = ((const float4*)p)[t];
    float s = v.x + v.y + v.z + v.w;
    float q = v.x * v.x + v.y * v.y + v.z * v.z + v.w * v.w;
#pragma unroll
    for (int off = 16; off > 0; off >>= 1) {
        s += __shfl_xor_sync(0xffffffffu, s, off);
        q += __shfl_xor_sync(0xffffffffu, q, off);
    }
    __shared__ float rs_[4], rq_[4];
    if ((t & 31) == 0) { rs_[t >> 5] = s; rq_[t >> 5] = q; }
    __syncthreads();
    s = rs_[0] + rs_[1] + rs_[2] + rs_[3];
    q = rq_[0] + rq_[1] + rq_[2] + rq_[3];
    float mean = s * (1.f / 512.f);
    float var = q * (1.f / 512.f) - mean * mean;
    float r = rsqrtf(var + 1e-5f);
    float4 gv = ((const float4*)gvec)[t];
    float4 bv = ((const float4*)bvec)[t];
    float xn;
    xn = (v.x - mean) * r * gv.x + bv.x; v.x = 0.5f * xn * (1.f + erff(xn * 0.70710678118654752f));
    xn = (v.y - mean) * r * gv.y + bv.y; v.y = 0.5f * xn * (1.f + erff(xn * 0.70710678118654752f));
    xn = (v.z - mean) * r * gv.z + bv.z; v.z = 0.5f * xn * (1.f + erff(xn * 0.70710678118654752f));
    xn = (v.w - mean) * r * gv.w + bv.w; v.w = 0.5f * xn * (1.f + erff(xn * 0.70710678118654752f));
    ((float4*)p)[t] = v;
}

// ---------------------------------------------------------------------------
extern "C" void kernel_launch(void* const* d_in, const int* in_sizes, int n_in,
                              void* d_out, int out_size)
{
    const float* x0  = (const float*)d_in[0];
    const float* x1  = (const float*)d_in[1];
    const float* Wqk = (const float*)d_in[2];
    const float* bqk = (const float*)d_in[3];
    const float* Wv  = (const float*)d_in[4];
    const float* bv  = (const float*)d_in[5];
    const float* Wo  = (const float*)d_in[6];
    const float* bo  = (const float*)d_in[7];
    const float* W1  = (const float*)d_in[8];
    const float* b1  = (const float*)d_in[9];
    const float* lng = (const float*)d_in[10];
    const float* lnb = (const float*)d_in[11];
    const float* W2  = (const float*)d_in[12];
    const float* b2  = (const float*)d_in[13];
    float* out = (float*)d_out;

    (void)in_sizes; (void)n_in; (void)out_size;

    static const int ATTN_SMEM = 174080;
    cudaFuncSetAttribute(attn_mma,
                         cudaFuncAttributeMaxDynamicSharedMemorySize, ATTN_SMEM);

    // 1) fused qk/v projection (both inputs, both weight mats)
    mgemm<0><<<dim3(4, 128), 256>>>(Wqk, Wv, bqk, bv, x0, x1, nullptr, 256, 256);
    // 2) bidirectional flash attention (tf32 mma)
    attn_mma<<<dim3(8, 16, 2), 256, ATTN_SMEM>>>();
    // 3) x -> cat cols [0,256)
    copy_x_kernel<<<4096, 256>>>(x0, x1);
    // 4) Wo projection -> cat cols [256,512)
    mgemm<1><<<dim3(2, 128), 256>>>(Wo, nullptr, bo, nullptr, nullptr, nullptr, nullptr, 256, 256);
    // 5) FFN GEMM1
    mgemm<2><<<dim3(4, 128), 256>>>(W1, nullptr, b1, nullptr, nullptr, nullptr, nullptr, 512, 512);
    // 6) LayerNorm + GELU (in place)
    ln_gelu_kernel<<<16384, 128>>>(lng, lnb);
    // 7) FFN GEMM2 + bias + residual -> d_out
    mgemm<3><<<dim3(2, 128), 256>>>(W2, nullptr, b2, nullptr, x0, x1, out, 512, 256);
}

// round 4
// speedup vs baseline: 3.3902x; 1.2347x over previous
#include <cuda_runtime.h>
#include <cstdint>

#define NB 4
#define NN 2048
#define NE 256
#define NH 4
#define ND 64
#define NE2 512
#define NTOK 16384               // 2 * B * N
#define PER (NB*NH*NN*ND)
#define QK_SCALE 0.35355339059327373f   // 64^-0.25

// ---------------- scratch (device globals; no allocation allowed) ----------
__device__ float g_qk[2][PER];            // pre-rounded tf32 values
__device__ float g_v [2][PER];            // pre-rounded
__device__ float g_am[NTOK*NE];           // attention out (pre-rounded)
__device__ float g_mo[NTOK*NE];           // m @ Wo + bo   (pre-rounded)
__device__ float g_h1[NTOK*NE2];          // FFN1 out (raw), then LN+gelu (pre-rounded)
__device__ float g_xtf[NTOK*NE];          // x0|x1 pre-rounded
__device__ float g_wqk[NE*NE], g_wv[NE*NE], g_wo[NE*NE];
__device__ float g_w1[NE2*NE2], g_w2[NE2*NE];

// ---------------- helpers ---------------------------------------------------
__device__ __forceinline__ uint32_t f2tf(float x) {
    uint32_t r; asm("cvt.rna.tf32.f32 %0, %1;" : "=r"(r) : "f"(x)); return r;
}
__device__ __forceinline__ float rtf(float x) { return __uint_as_float(f2tf(x)); }
__device__ __forceinline__ void cpa16(uint32_t s, const void* g) {
    asm volatile("cp.async.cg.shared.global [%0], [%1], 16;" :: "r"(s), "l"(g));
}
__device__ __forceinline__ void cp_commit() { asm volatile("cp.async.commit_group;"); }
template<int N> __device__ __forceinline__ void cp_wait() {
    asm volatile("cp.async.wait_group %0;" :: "n"(N));
}
__device__ __forceinline__ void mma8(float* d, const uint32_t* a, const uint32_t* b) {
    asm volatile(
        "mma.sync.aligned.m16n8k8.row.col.f32.tf32.tf32.f32 "
        "{%0,%1,%2,%3}, {%4,%5,%6,%7}, {%8,%9}, {%0,%1,%2,%3};\n"
        : "+f"(d[0]), "+f"(d[1]), "+f"(d[2]), "+f"(d[3])
        : "r"(a[0]), "r"(a[1]), "r"(a[2]), "r"(a[3]), "r"(b[0]), "r"(b[1]));
}

// ---------------- pre-round x and all weights to tf32 -----------------------
__global__ void cvt_pre(const float* __restrict__ x0, const float* __restrict__ x1,
                        const float* __restrict__ Wqk, const float* __restrict__ Wv,
                        const float* __restrict__ Wo,  const float* __restrict__ W1,
                        const float* __restrict__ W2)
{
    int i = blockIdx.x * 256 + threadIdx.x;    // float4 index, total 1196032
    const float4* s; float4* d; int j;
    if      (i < 524288)  { j = i;           s = (const float4*)x0;  d = (float4*)g_xtf + j; }
    else if (i < 1048576) { j = i - 524288;  s = (const float4*)x1;  d = (float4*)g_xtf + 524288 + j; }
    else if (i < 1064960) { j = i - 1048576; s = (const float4*)Wqk; d = (float4*)g_wqk + j; }
    else if (i < 1081344) { j = i - 1064960; s = (const float4*)Wv;  d = (float4*)g_wv  + j; }
    else if (i < 1097728) { j = i - 1081344; s = (const float4*)Wo;  d = (float4*)g_wo  + j; }
    else if (i < 1163264) { j = i - 1097728; s = (const float4*)W1;  d = (float4*)g_w1  + j; }
    else                  { j = i - 1163264; s = (const float4*)W2;  d = (float4*)g_w2  + j; }
    float4 v = s[j];
    v.x = rtf(v.x); v.y = rtf(v.y); v.z = rtf(v.z); v.w = rtf(v.w);
    *d = v;
}

// ---------------- tf32 mma GEMM, 128x128 block, cp.async 3-stage ------------
// MODE 0: A=g_xtf  [16384,256], B=Wqk|Wv -> g_qk (scaled,rounded)/g_v (rounded)
// MODE 1: A=g_am   [16384,256], B=Wo     -> g_mo (+bo, rounded)
// MODE 2: A=xtf|mo [16384,512], B=W1     -> g_h1 (+b1, raw)
// MODE 3: A=g_h1   [16384,512], B=W2     -> out  (+b2 + residual)
template<int MODE>
__global__ void __launch_bounds__(256, 2) mgemm(
    const float* __restrict__ ba, const float* __restrict__ bb,
    const float* __restrict__ r0, const float* __restrict__ r1,
    float* __restrict__ out)
{
    constexpr int K   = (MODE >= 2) ? 512 : 256;
    constexpr int LDB = (MODE == 2) ? 512 : 256;
    constexpr int LDA = (MODE == 3) ? 512 : 256;
    constexpr int KT  = K / 32;

    extern __shared__ uint32_t sm[];
    const uint32_t smb = (uint32_t)__cvta_generic_to_shared(sm);
    const int tid = threadIdx.x, wid = tid >> 5, lane = tid & 31;
    const int wm = wid & 3, wn = wid >> 2, g = lane >> 2, t = lane & 3;
    const int bx = blockIdx.x, by = blockIdx.y;

    auto copy_tile = [&](int kt, int st) {
        const int k0 = kt * 32;
        const float* Ab;
        if constexpr (MODE == 0)      Ab = g_xtf + k0;
        else if constexpr (MODE == 1) Ab = g_am + k0;
        else if constexpr (MODE == 2) Ab = (k0 < 256) ? (g_xtf + k0) : (g_mo + (k0 - 256));
        else                          Ab = g_h1 + k0;
        Ab += (size_t)by * 128 * LDA;
        const float* Bb;
        if constexpr (MODE == 0)      Bb = (bx < 2) ? (g_wqk + bx * 128) : (g_wv + (bx - 2) * 128);
        else if constexpr (MODE == 1) Bb = g_wo + bx * 128;
        else if constexpr (MODE == 2) Bb = g_w1 + bx * 128;
        else                          Bb = g_w2 + bx * 128;
        Bb += (size_t)k0 * LDB;
        uint32_t sA = smb + (uint32_t)(st * 8960) * 4;
        uint32_t sB = sA + 4608 * 4;
#pragma unroll
        for (int i = 0; i < 4; i++) {
            int ci = i * 256 + tid, row = ci >> 3, cw = (ci & 7) * 4;
            cpa16(sA + (uint32_t)(row * 36 + cw) * 4, Ab + (size_t)row * LDA + cw);
        }
#pragma unroll
        for (int i = 0; i < 4; i++) {
            int ci = i * 256 + tid, row = ci >> 5, cw = (ci & 31) * 4;
            cpa16(sB + (uint32_t)(row * 136 + cw) * 4, Bb + (size_t)row * LDB + cw);
        }
        cp_commit();
    };

    float acc[2][8][4] = {};

    copy_tile(0, 0);
    copy_tile(1, 1);

    for (int kt = 0; kt < KT; kt++) {
        if (kt + 2 < KT) cp_wait<1>(); else cp_wait<0>();
        __syncthreads();
        if (kt + 2 < KT) copy_tile(kt + 2, (kt + 2) % 3);

        const uint32_t* As = sm + (kt % 3) * 8960;
        const uint32_t* Bs = As + 4608;
#pragma unroll
        for (int ks = 0; ks < 32; ks += 8) {
            uint32_t af[2][4], bf[8][2];
#pragma unroll
            for (int mt = 0; mt < 2; mt++) {
                int mr = wm * 32 + mt * 16 + g;
                af[mt][0] = As[mr * 36 + ks + t];
                af[mt][1] = As[(mr + 8) * 36 + ks + t];
                af[mt][2] = As[mr * 36 + ks + t + 4];
                af[mt][3] = As[(mr + 8) * 36 + ks + t + 4];
            }
#pragma unroll
            for (int nt = 0; nt < 8; nt++) {
                int nc = wn * 64 + nt * 8 + g;
                bf[nt][0] = Bs[(ks + t) * 136 + nc];
                bf[nt][1] = Bs[(ks + t + 4) * 136 + nc];
            }
#pragma unroll
            for (int mt = 0; mt < 2; mt++)
#pragma unroll
                for (int nt = 0; nt < 8; nt++)
                    mma8(acc[mt][nt], af[mt], bf[nt]);
        }
    }

    // epilogue
#pragma unroll
    for (int mt = 0; mt < 2; mt++)
#pragma unroll
    for (int h = 0; h < 2; h++) {
        int r = by * 128 + wm * 32 + mt * 16 + g + h * 8;
#pragma unroll
        for (int nt = 0; nt < 8; nt++) {
            int c = bx * 128 + wn * 64 + nt * 8 + 2 * t;
            float v0 = acc[mt][nt][h * 2 + 0];
            float v1 = acc[mt][nt][h * 2 + 1];
            if constexpr (MODE == 0) {
                int src = r >> 13, rl = r & 8191;
                int b = rl >> 11, n = rl & 2047;
                if (c < 256) {
                    float2 b2 = *(const float2*)&ba[c];
                    int hh = c >> 6, d = c & 63;
                    float2 w;
                    w.x = rtf((v0 + b2.x) * QK_SCALE);
                    w.y = rtf((v1 + b2.y) * QK_SCALE);
                    *(float2*)&g_qk[src][(((size_t)(b * NH + hh)) * NN + n) * ND + d] = w;
                } else {
                    int c2 = c - 256;
                    float2 b2 = *(const float2*)&bb[c2];
                    int hh = c2 >> 6, d = c2 & 63;
                    float2 w; w.x = rtf(v0 + b2.x); w.y = rtf(v1 + b2.y);
                    *(float2*)&g_v[src][(((size_t)(b * NH + hh)) * NN + n) * ND + d] = w;
                }
            } else if constexpr (MODE == 1) {
                float2 b2 = *(const float2*)&ba[c];
                float2 w; w.x = rtf(v0 + b2.x); w.y = rtf(v1 + b2.y);
                *(float2*)&g_mo[(size_t)r * NE + c] = w;
            } else if constexpr (MODE == 2) {
                float2 b2 = *(const float2*)&ba[c];
                float2 w; w.x = v0 + b2.x; w.y = v1 + b2.y;
                *(float2*)&g_h1[(size_t)r * NE2 + c] = w;
            } else {
                int src = r >> 13, rl = r & 8191;
                const float* xr = src ? r1 : r0;
                float2 b2 = *(const float2*)&ba[c];
                float2 xv = *(const float2*)&xr[(size_t)rl * NE + c];
                float2 w; w.x = v0 + b2.x + xv.x; w.y = v1 + b2.y + xv.y;
                *(float2*)&out[(size_t)r * NE + c] = w;
            }
        }
    }
}

// ---------------- flash attention: Q in regs, cp.async 3-stage KV -----------
// smem (words): Ps 256x68 = 17408 | Ks 3 x 64x68 = 13056 | Vs 3 x 64x72 = 13824
// total 44288 words = 177152 B
__global__ void __launch_bounds__(256, 1) attn_mma()
{
    extern __shared__ uint32_t smx[];
    const uint32_t smb = (uint32_t)__cvta_generic_to_shared(smx);
    uint32_t* Ps = smx;

    const int qt = blockIdx.x, bh = blockIdx.y, dir = blockIdx.z;
    const int tid = threadIdx.x, wid = tid >> 5, lane = tid & 31;
    const int g = lane >> 2, t = lane & 3, mq = wid * 32;

    const float* Q  = g_qk[dir]     + (size_t)bh * NN * ND + (size_t)qt * 256 * ND;
    const float* Kp = g_qk[dir ^ 1] + (size_t)bh * NN * ND;
    const float* Vp = g_v [dir ^ 1] + (size_t)bh * NN * ND;

    // stage Q through Ps region, then lift fragments to registers
    {
        int rr = tid >> 3, cc = (tid & 7) * 8;
#pragma unroll
        for (int i = 0; i < 8; i++) {
            int row = i * 32 + rr;
            float4 a = *(const float4*)(Q + (size_t)row * ND + cc);
            float4 b = *(const float4*)(Q + (size_t)row * ND + cc + 4);
            *(float4*)&Ps[row * 68 + cc]     = a;
            *(float4*)&Ps[row * 68 + cc + 4] = b;
        }
    }
    __syncthreads();

    uint32_t qf[2][8][4];
#pragma unroll
    for (int mt = 0; mt < 2; mt++) {
        int mr = mq + mt * 16 + g;
#pragma unroll
        for (int k8 = 0; k8 < 8; k8++) {
            qf[mt][k8][0] = Ps[mr * 68 + k8 * 8 + t];
            qf[mt][k8][1] = Ps[(mr + 8) * 68 + k8 * 8 + t];
            qf[mt][k8][2] = Ps[mr * 68 + k8 * 8 + t + 4];
            qf[mt][k8][3] = Ps[(mr + 8) * 68 + k8 * 8 + t + 4];
        }
    }
    __syncthreads();

    auto load_kv = [&](int j, int st) {
        uint32_t sK = smb + (uint32_t)(17408 + st * 4352) * 4;
        uint32_t sV = smb + (uint32_t)(30464 + st * 4608) * 4;
        const float* kb = Kp + (size_t)j * 64 * ND;
        const float* vb = Vp + (size_t)j * 64 * ND;
#pragma unroll
        for (int i = 0; i < 4; i++) {
            int ci = i * 256 + tid, row = ci >> 4, cw = (ci & 15) * 4;
            cpa16(sK + (uint32_t)(row * 68 + cw) * 4, kb + row * 64 + cw);
            cpa16(sV + (uint32_t)(row * 72 + cw) * 4, vb + row * 64 + cw);
        }
        cp_commit();
    };

    float o[2][8][4] = {};
    float m_s[4] = {-1e30f, -1e30f, -1e30f, -1e30f};
    float l_s[4] = {};

    load_kv(0, 0);
    load_kv(1, 1);

    for (int j = 0; j < 32; j++) {
        if (j + 2 < 32) cp_wait<1>(); else cp_wait<0>();
        __syncthreads();
        if (j + 2 < 32) load_kv(j + 2, (j + 2) % 3);

        const uint32_t* Ks = smx + 17408 + (j % 3) * 4352;
        const uint32_t* Vs = smx + 30464 + (j % 3) * 4608;

        // S = Q K^T
        float s[2][8][4] = {};
#pragma unroll
        for (int ks = 0; ks < 64; ks += 8) {
            uint32_t bf[8][2];
#pragma unroll
            for (int nt = 0; nt < 8; nt++) {
                bf[nt][0] = Ks[(nt * 8 + g) * 68 + ks + t];
                bf[nt][1] = Ks[(nt * 8 + g) * 68 + ks + t + 4];
            }
#pragma unroll
            for (int mt = 0; mt < 2; mt++)
#pragma unroll
                for (int nt = 0; nt < 8; nt++)
                    mma8(s[mt][nt], qf[mt][ks >> 3], bf[nt]);
        }

        // online softmax (rows are warp-private; Ps rows mq..mq+31)
#pragma unroll
        for (int mt = 0; mt < 2; mt++)
#pragma unroll
        for (int h = 0; h < 2; h++) {
            const int si = mt * 2 + h;
            float mx = -1e30f;
#pragma unroll
            for (int nt = 0; nt < 8; nt++)
                mx = fmaxf(mx, fmaxf(s[mt][nt][2 * h], s[mt][nt][2 * h + 1]));
            mx = fmaxf(mx, __shfl_xor_sync(0xffffffffu, mx, 1));
            mx = fmaxf(mx, __shfl_xor_sync(0xffffffffu, mx, 2));
            float mn = fmaxf(m_s[si], mx);
            float corr = __expf(m_s[si] - mn);
            m_s[si] = mn;
            float ls = 0.f;
            const int prow = mq + mt * 16 + g + h * 8;
#pragma unroll
            for (int nt = 0; nt < 8; nt++) {
                float p0 = __uint_as_float(f2tf(__expf(s[mt][nt][2 * h] - mn)));
                float p1 = __uint_as_float(f2tf(__expf(s[mt][nt][2 * h + 1] - mn)));
                ls += p0 + p1;
                uint2 pv; pv.x = __float_as_uint(p0); pv.y = __float_as_uint(p1);
                *(uint2*)&Ps[prow * 68 + nt * 8 + 2 * t] = pv;
            }
            ls += __shfl_xor_sync(0xffffffffu, ls, 1);
            ls += __shfl_xor_sync(0xffffffffu, ls, 2);
            l_s[si] = l_s[si] * corr + ls;
#pragma unroll
            for (int nt = 0; nt < 8; nt++) {
                o[mt][nt][2 * h] *= corr;
                o[mt][nt][2 * h + 1] *= corr;
            }
        }
        __syncwarp();

        // O += P V
#pragma unroll
        for (int ks = 0; ks < 64; ks += 8) {
            uint32_t af[2][4], bf[8][2];
#pragma unroll
            for (int mt = 0; mt < 2; mt++) {
                int mr = mq + mt * 16 + g;
                af[mt][0] = Ps[mr * 68 + ks + t];
                af[mt][1] = Ps[(mr + 8) * 68 + ks + t];
                af[mt][2] = Ps[mr * 68 + ks + t + 4];
                af[mt][3] = Ps[(mr + 8) * 68 + ks + t + 4];
            }
#pragma unroll
            for (int nt = 0; nt < 8; nt++) {
                bf[nt][0] = Vs[(ks + t) * 72 + nt * 8 + g];
                bf[nt][1] = Vs[(ks + t + 4) * 72 + nt * 8 + g];
            }
#pragma unroll
            for (int mt = 0; mt < 2; mt++)
#pragma unroll
                for (int nt = 0; nt < 8; nt++)
                    mma8(o[mt][nt], af[mt], bf[nt]);
        }
    }

    const int b = bh >> 2, hd = bh & 3;
#pragma unroll
    for (int mt = 0; mt < 2; mt++)
#pragma unroll
    for (int h = 0; h < 2; h++) {
        const int si = mt * 2 + h;
        float inv = 1.f / l_s[si];
        int n = qt * 256 + mq + mt * 16 + g + h * 8;
        size_t base = ((size_t)(dir * 8192 + b * NN + n)) * NE + hd * ND;
#pragma unroll
        for (int nt = 0; nt < 8; nt++) {
            float2 w;
            w.x = rtf(o[mt][nt][2 * h] * inv);
            w.y = rtf(o[mt][nt][2 * h + 1] * inv);
            *(float2*)&g_am[base + nt * 8 + 2 * t] = w;
        }
    }
}

// ---------------- LayerNorm(512) + exact GELU, in-place, tf32-rounded out ---
__global__ void __launch_bounds__(128) ln_gelu_kernel(
    const float* __restrict__ gvec, const float* __restrict__ bvec)
{
    float* p = g_h1 + (size_t)blockIdx.x * NE2;
    int t = threadIdx.x;
    float4 v = ((const float4*)p)[t];
    float s = v.x + v.y + v.z + v.w;
    float q = v.x * v.x + v.y * v.y + v.z * v.z + v.w * v.w;
#pragma unroll
    for (int off = 16; off > 0; off >>= 1) {
        s += __shfl_xor_sync(0xffffffffu, s, off);
        q += __shfl_xor_sync(0xffffffffu, q, off);
    }
    __shared__ float rs_[4], rq_[4];
    if ((t & 31) == 0) { rs_[t >> 5] = s; rq_[t >> 5] = q; }
    __syncthreads();
    s = rs_[0] + rs_[1] + rs_[2] + rs_[3];
    q = rq_[0] + rq_[1] + rq_[2] + rq_[3];
    float mean = s * (1.f / 512.f);
    float var = q * (1.f / 512.f) - mean * mean;
    float r = rsqrtf(var + 1e-5f);
    float4 gv = ((const float4*)gvec)[t];
    float4 bv = ((const float4*)bvec)[t];
    float xn;
    xn = (v.x - mean) * r * gv.x + bv.x; v.x = rtf(0.5f * xn * (1.f + erff(xn * 0.70710678118654752f)));
    xn = (v.y - mean) * r * gv.y + bv.y; v.y = rtf(0.5f * xn * (1.f + erff(xn * 0.70710678118654752f)));
    xn = (v.z - mean) * r * gv.z + bv.z; v.z = rtf(0.5f * xn * (1.f + erff(xn * 0.70710678118654752f)));
    xn = (v.w - mean) * r * gv.w + bv.w; v.w = rtf(0.5f * xn * (1.f + erff(xn * 0.70710678118654752f)));
    ((float4*)p)[t] = v;
}

// ---------------------------------------------------------------------------
extern "C" void kernel_launch(void* const* d_in, const int* in_sizes, int n_in,
                              void* d_out, int out_size)
{
    const float* x0  = (const float*)d_in[0];
    const float* x1  = (const float*)d_in[1];
    const float* Wqk = (const float*)d_in[2];
    const float* bqk = (const float*)d_in[3];
    const float* Wv  = (const float*)d_in[4];
    const float* bv  = (const float*)d_in[5];
    const float* Wo  = (const float*)d_in[6];
    const float* bo  = (const float*)d_in[7];
    const float* W1  = (const float*)d_in[8];
    const float* b1  = (const float*)d_in[9];
    const float* lng = (const float*)d_in[10];
    const float* lnb = (const float*)d_in[11];
    const float* W2  = (const float*)d_in[12];
    const float* b2  = (const float*)d_in[13];
    float* out = (float*)d_out;
    (void)in_sizes; (void)n_in; (void)out_size;

    const int GEMM_SMEM = 107520;   // 3 stages x 8960 words
    const int ATTN_SMEM = 177152;   // 44288 words
    cudaFuncSetAttribute(mgemm<0>, cudaFuncAttributeMaxDynamicSharedMemorySize, GEMM_SMEM);
    cudaFuncSetAttribute(mgemm<1>, cudaFuncAttributeMaxDynamicSharedMemorySize, GEMM_SMEM);
    cudaFuncSetAttribute(mgemm<2>, cudaFuncAttributeMaxDynamicSharedMemorySize, GEMM_SMEM);
    cudaFuncSetAttribute(mgemm<3>, cudaFuncAttributeMaxDynamicSharedMemorySize, GEMM_SMEM);
    cudaFuncSetAttribute(attn_mma, cudaFuncAttributeMaxDynamicSharedMemorySize, ATTN_SMEM);

    // 0) pre-round x + weights to tf32
    cvt_pre<<<4672, 256>>>(x0, x1, Wqk, Wv, Wo, W1, W2);
    // 1) fused qk/v projection
    mgemm<0><<<dim3(4, 128), 256, GEMM_SMEM>>>(bqk, bv, x0, x1, nullptr);
    // 2) bidirectional flash attention
    attn_mma<<<dim3(8, 16, 2), 256, ATTN_SMEM>>>();
    // 3) Wo projection -> g_mo
    mgemm<1><<<dim3(2, 128), 256, GEMM_SMEM>>>(bo, nullptr, x0, x1, nullptr);
    // 4) FFN GEMM1 ([x | mo] @ W1) -> g_h1
    mgemm<2><<<dim3(4, 128), 256, GEMM_SMEM>>>(b1, nullptr, x0, x1, nullptr);
    // 5) LayerNorm + GELU (in place, rounded)
    ln_gelu_kernel<<<16384, 128>>>(lng, lnb);
    // 6) FFN GEMM2 + bias + residual -> out
    mgemm<3><<<dim3(2, 128), 256, GEMM_SMEM>>>(b2, nullptr, x0, x1, out);
}

// round 6
// speedup vs baseline: 3.4977x; 1.0317x over previous
#include <cuda_runtime.h>
#include <cstdint>

#define NB 4
#define NN 2048
#define NE 256
#define NH 4
#define ND 64
#define NE2 512
#define NTOK 16384               // 2 * B * N
#define PER (NB*NH*NN*ND)
#define QK_SCALE 0.35355339059327373f   // 64^-0.25

// ---------------- scratch (device globals; no allocation allowed) ----------
__device__ float g_qk[2][PER];            // pre-rounded tf32 values
__device__ float g_v [2][PER];            // pre-rounded
__device__ float g_am[NTOK*NE];           // attention out (pre-rounded)
__device__ float g_mo[NTOK*NE];           // m @ Wo + bo   (pre-rounded)
__device__ float g_h1[NTOK*NE2];          // FFN1 out (raw), then LN+gelu (pre-rounded)
__device__ float g_xtf[NTOK*NE];          // x0|x1 pre-rounded
__device__ float g_wqk[NE*NE], g_wv[NE*NE], g_wo[NE*NE];
__device__ float g_w1[NE2*NE2], g_w2[NE2*NE];

// ---------------- helpers ---------------------------------------------------
__device__ __forceinline__ uint32_t f2tf(float x) {
    uint32_t r; asm("cvt.rna.tf32.f32 %0, %1;" : "=r"(r) : "f"(x)); return r;
}
__device__ __forceinline__ float rtf(float x) { return __uint_as_float(f2tf(x)); }
__device__ __forceinline__ void cpa16(uint32_t s, const void* g) {
    asm volatile("cp.async.cg.shared.global [%0], [%1], 16;" :: "r"(s), "l"(g));
}
__device__ __forceinline__ void cp_commit() { asm volatile("cp.async.commit_group;"); }
template<int N> __device__ __forceinline__ void cp_wait() {
    asm volatile("cp.async.wait_group %0;" :: "n"(N));
}
__device__ __forceinline__ void mma8(float* d, const uint32_t* a, const uint32_t* b) {
    asm volatile(
        "mma.sync.aligned.m16n8k8.row.col.f32.tf32.tf32.f32 "
        "{%0,%1,%2,%3}, {%4,%5,%6,%7}, {%8,%9}, {%0,%1,%2,%3};\n"
        : "+f"(d[0]), "+f"(d[1]), "+f"(d[2]), "+f"(d[3])
        : "r"(a[0]), "r"(a[1]), "r"(a[2]), "r"(a[3]), "r"(b[0]), "r"(b[1]));
}

// ---------------- pre-round x and all weights to tf32 -----------------------
__global__ void cvt_pre(const float* __restrict__ x0, const float* __restrict__ x1,
                        const float* __restrict__ Wqk, const float* __restrict__ Wv,
                        const float* __restrict__ Wo,  const float* __restrict__ W1,
                        const float* __restrict__ W2)
{
    int i = blockIdx.x * 256 + threadIdx.x;    // float4 index, total 1196032
    const float4* s; float4* d; int j;
    if      (i < 524288)  { j = i;           s = (const float4*)x0;  d = (float4*)g_xtf + j; }
    else if (i < 1048576) { j = i - 524288;  s = (const float4*)x1;  d = (float4*)g_xtf + 524288 + j; }
    else if (i < 1064960) { j = i - 1048576; s = (const float4*)Wqk; d = (float4*)g_wqk + j; }
    else if (i < 1081344) { j = i - 1064960; s = (const float4*)Wv;  d = (float4*)g_wv  + j; }
    else if (i < 1097728) { j = i - 1081344; s = (const float4*)Wo;  d = (float4*)g_wo  + j; }
    else if (i < 1163264) { j = i - 1097728; s = (const float4*)W1;  d = (float4*)g_w1  + j; }
    else                  { j = i - 1163264; s = (const float4*)W2;  d = (float4*)g_w2  + j; }
    float4 v = s[j];
    v.x = rtf(v.x); v.y = rtf(v.y); v.z = rtf(v.z); v.w = rtf(v.w);
    *d = v;
}

// ---------------- tf32 mma GEMM, 128x128 block, cp.async 3-stage ------------
// MODE 0: A=g_xtf  [16384,256], B=Wqk|Wv -> g_qk (scaled,rounded)/g_v (rounded)
// MODE 1: A=g_am   [16384,256], B=Wo     -> g_mo (+bo, rounded)
// MODE 2: A=xtf|mo [16384,512], B=W1     -> g_h1 (+b1, raw)
// MODE 3: A=g_h1   [16384,512], B=W2     -> out  (+b2 + residual)
template<int MODE>
__global__ void __launch_bounds__(256, 2) mgemm(
    const float* __restrict__ ba, const float* __restrict__ bb,
    const float* __restrict__ r0, const float* __restrict__ r1,
    float* __restrict__ out)
{
    constexpr int K   = (MODE >= 2) ? 512 : 256;
    constexpr int LDB = (MODE == 2) ? 512 : 256;
    constexpr int LDA = (MODE == 3) ? 512 : 256;
    constexpr int KT  = K / 32;

    extern __shared__ uint32_t sm[];
    const uint32_t smb = (uint32_t)__cvta_generic_to_shared(sm);
    const int tid = threadIdx.x, wid = tid >> 5, lane = tid & 31;
    const int wm = wid & 3, wn = wid >> 2, g = lane >> 2, t = lane & 3;
    const int bx = blockIdx.x, by = blockIdx.y;

    auto copy_tile = [&](int kt, int st) {
        const int k0 = kt * 32;
        const float* Ab;
        if constexpr (MODE == 0)      Ab = g_xtf + k0;
        else if constexpr (MODE == 1) Ab = g_am + k0;
        else if constexpr (MODE == 2) Ab = (k0 < 256) ? (g_xtf + k0) : (g_mo + (k0 - 256));
        else                          Ab = g_h1 + k0;
        Ab += (size_t)by * 128 * LDA;
        const float* Bb;
        if constexpr (MODE == 0)      Bb = (bx < 2) ? (g_wqk + bx * 128) : (g_wv + (bx - 2) * 128);
        else if constexpr (MODE == 1) Bb = g_wo + bx * 128;
        else if constexpr (MODE == 2) Bb = g_w1 + bx * 128;
        else                          Bb = g_w2 + bx * 128;
        Bb += (size_t)k0 * LDB;
        uint32_t sA = smb + (uint32_t)(st * 8960) * 4;
        uint32_t sB = sA + 4608 * 4;
#pragma unroll
        for (int i = 0; i < 4; i++) {
            int ci = i * 256 + tid, row = ci >> 3, cw = (ci & 7) * 4;
            cpa16(sA + (uint32_t)(row * 36 + cw) * 4, Ab + (size_t)row * LDA + cw);
        }
#pragma unroll
        for (int i = 0; i < 4; i++) {
            int ci = i * 256 + tid, row = ci >> 5, cw = (ci & 31) * 4;
            cpa16(sB + (uint32_t)(row * 136 + cw) * 4, Bb + (size_t)row * LDB + cw);
        }
        cp_commit();
    };

    float acc[2][8][4] = {};

    copy_tile(0, 0);
    copy_tile(1, 1);

    for (int kt = 0; kt < KT; kt++) {
        if (kt + 2 < KT) cp_wait<1>(); else cp_wait<0>();
        __syncthreads();
        if (kt + 2 < KT) copy_tile(kt + 2, (kt + 2) % 3);

        const uint32_t* As = sm + (kt % 3) * 8960;
        const uint32_t* Bs = As + 4608;
#pragma unroll
        for (int ks = 0; ks < 32; ks += 8) {
            uint32_t af[2][4], bf[8][2];
#pragma unroll
            for (int mt = 0; mt < 2; mt++) {
                int mr = wm * 32 + mt * 16 + g;
                af[mt][0] = As[mr * 36 + ks + t];
                af[mt][1] = As[(mr + 8) * 36 + ks + t];
                af[mt][2] = As[mr * 36 + ks + t + 4];
                af[mt][3] = As[(mr + 8) * 36 + ks + t + 4];
            }
#pragma unroll
            for (int nt = 0; nt < 8; nt++) {
                int nc = wn * 64 + nt * 8 + g;
                bf[nt][0] = Bs[(ks + t) * 136 + nc];
                bf[nt][1] = Bs[(ks + t + 4) * 136 + nc];
            }
#pragma unroll
            for (int mt = 0; mt < 2; mt++)
#pragma unroll
                for (int nt = 0; nt < 8; nt++)
                    mma8(acc[mt][nt], af[mt], bf[nt]);
        }
    }

    // epilogue
#pragma unroll
    for (int mt = 0; mt < 2; mt++)
#pragma unroll
    for (int h = 0; h < 2; h++) {
        int r = by * 128 + wm * 32 + mt * 16 + g + h * 8;
#pragma unroll
        for (int nt = 0; nt < 8; nt++) {
            int c = bx * 128 + wn * 64 + nt * 8 + 2 * t;
            float v0 = acc[mt][nt][h * 2 + 0];
            float v1 = acc[mt][nt][h * 2 + 1];
            if constexpr (MODE == 0) {
                int src = r >> 13, rl = r & 8191;
                int b = rl >> 11, n = rl & 2047;
                if (c < 256) {
                    float2 b2 = *(const float2*)&ba[c];
                    int hh = c >> 6, d = c & 63;
                    float2 w;
                    w.x = rtf((v0 + b2.x) * QK_SCALE);
                    w.y = rtf((v1 + b2.y) * QK_SCALE);
                    *(float2*)&g_qk[src][(((size_t)(b * NH + hh)) * NN + n) * ND + d] = w;
                } else {
                    int c2 = c - 256;
                    float2 b2 = *(const float2*)&bb[c2];
                    int hh = c2 >> 6, d = c2 & 63;
                    float2 w; w.x = rtf(v0 + b2.x); w.y = rtf(v1 + b2.y);
                    *(float2*)&g_v[src][(((size_t)(b * NH + hh)) * NN + n) * ND + d] = w;
                }
            } else if constexpr (MODE == 1) {
                float2 b2 = *(const float2*)&ba[c];
                float2 w; w.x = rtf(v0 + b2.x); w.y = rtf(v1 + b2.y);
                *(float2*)&g_mo[(size_t)r * NE + c] = w;
            } else if constexpr (MODE == 2) {
                float2 b2 = *(const float2*)&ba[c];
                float2 w; w.x = v0 + b2.x; w.y = v1 + b2.y;
                *(float2*)&g_h1[(size_t)r * NE2 + c] = w;
            } else {
                int src = r >> 13, rl = r & 8191;
                const float* xr = src ? r1 : r0;
                float2 b2 = *(const float2*)&ba[c];
                float2 xv = *(const float2*)&xr[(size_t)rl * NE + c];
                float2 w; w.x = v0 + b2.x + xv.x; w.y = v1 + b2.y + xv.y;
                *(float2*)&out[(size_t)r * NE + c] = w;
            }
        }
    }
}

// ---------------- flash attention: no-max softmax, 2 blocks/SM ---------------
// block = 128 threads (4 warps), Q-tile 128 rows, warp tile 32x64, 2-stage KV
// smem words: Ps 128x68 = 8704 | Ks 2 x 64x68 = 8704 | Vs 2 x 64x72 = 9216
// total 26624 words = 106496 B  -> 2 blocks/SM
__global__ void __launch_bounds__(128, 2) attn_mma()
{
    extern __shared__ uint32_t smx[];
    const uint32_t smb = (uint32_t)__cvta_generic_to_shared(smx);
    uint32_t* Ps = smx;

    const int qt = blockIdx.x, bh = blockIdx.y, dir = blockIdx.z;
    const int tid = threadIdx.x, wid = tid >> 5, lane = tid & 31;
    const int g = lane >> 2, t = lane & 3, mq = wid * 32;

    const float* Q  = g_qk[dir]     + (size_t)bh * NN * ND + (size_t)qt * 128 * ND;
    const float* Kp = g_qk[dir ^ 1] + (size_t)bh * NN * ND;
    const float* Vp = g_v [dir ^ 1] + (size_t)bh * NN * ND;

    // stage Q through Ps (one row per thread: 128 threads x 128 rows), then
    // lift fragments to registers
    {
        int row = tid;
#pragma unroll
        for (int i = 0; i < 16; i++)
            *(float4*)&Ps[row * 68 + i * 4] =
                *(const float4*)(Q + (size_t)row * ND + i * 4);
    }
    __syncthreads();

    uint32_t qf[2][8][4];
#pragma unroll
    for (int mt = 0; mt < 2; mt++) {
        int mr = mq + mt * 16 + g;
#pragma unroll
        for (int k8 = 0; k8 < 8; k8++) {
            qf[mt][k8][0] = Ps[mr * 68 + k8 * 8 + t];
            qf[mt][k8][1] = Ps[(mr + 8) * 68 + k8 * 8 + t];
            qf[mt][k8][2] = Ps[mr * 68 + k8 * 8 + t + 4];
            qf[mt][k8][3] = Ps[(mr + 8) * 68 + k8 * 8 + t + 4];
        }
    }
    __syncthreads();

    auto load_kv = [&](int j, int st) {
        uint32_t sK = smb + (uint32_t)(8704 + st * 4352) * 4;
        uint32_t sV = smb + (uint32_t)(17408 + st * 4608) * 4;
        const float* kb = Kp + (size_t)j * 64 * ND;
        const float* vb = Vp + (size_t)j * 64 * ND;
#pragma unroll
        for (int i = 0; i < 8; i++) {
            int ci = i * 128 + tid, row = ci >> 4, cw = (ci & 15) * 4;
            cpa16(sK + (uint32_t)(row * 68 + cw) * 4, kb + row * 64 + cw);
            cpa16(sV + (uint32_t)(row * 72 + cw) * 4, vb + row * 64 + cw);
        }
        cp_commit();
    };

    float o[2][8][4] = {};
    float l_s[4] = {};

    load_kv(0, 0);

    for (int j = 0; j < 32; j++) {
        cp_wait<0>();
        __syncthreads();
        if (j + 1 < 32) load_kv(j + 1, (j + 1) & 1);

        const uint32_t* Ks = smx + 8704 + (j & 1) * 4352;
        const uint32_t* Vs = smx + 17408 + (j & 1) * 4608;

        // S = Q K^T  (32 x 64 per warp)
        float s[2][8][4] = {};
#pragma unroll
        for (int ks = 0; ks < 64; ks += 8) {
            uint32_t bf[8][2];
#pragma unroll
            for (int nt = 0; nt < 8; nt++) {
                bf[nt][0] = Ks[(nt * 8 + g) * 68 + ks + t];
                bf[nt][1] = Ks[(nt * 8 + g) * 68 + ks + t + 4];
            }
#pragma unroll
            for (int mt = 0; mt < 2; mt++)
#pragma unroll
                for (int nt = 0; nt < 8; nt++)
                    mma8(s[mt][nt], qf[mt][ks >> 3], bf[nt]);
        }

        // no-max softmax: P = exp(S); per-thread l accumulation (reduced once at end)
#pragma unroll
        for (int mt = 0; mt < 2; mt++)
#pragma unroll
        for (int h = 0; h < 2; h++) {
            const int si = mt * 2 + h;
            const int prow = mq + mt * 16 + g + h * 8;
            float ls = 0.f;
#pragma unroll
            for (int nt = 0; nt < 8; nt++) {
                float p0 = __uint_as_float(f2tf(__expf(s[mt][nt][2 * h])));
                float p1 = __uint_as_float(f2tf(__expf(s[mt][nt][2 * h + 1])));
                ls += p0 + p1;
                uint2 pv; pv.x = __float_as_uint(p0); pv.y = __float_as_uint(p1);
                *(uint2*)&Ps[prow * 68 + nt * 8 + 2 * t] = pv;
            }
            l_s[si] += ls;
        }
        __syncwarp();

        // O += P V
#pragma unroll
        for (int ks = 0; ks < 64; ks += 8) {
            uint32_t af[2][4], bf[8][2];
#pragma unroll
            for (int mt = 0; mt < 2; mt++) {
                int mr = mq + mt * 16 + g;
                af[mt][0] = Ps[mr * 68 + ks + t];
                af[mt][1] = Ps[(mr + 8) * 68 + ks + t];
                af[mt][2] = Ps[mr * 68 + ks + t + 4];
                af[mt][3] = Ps[(mr + 8) * 68 + ks + t + 4];
            }
#pragma unroll
            for (int nt = 0; nt < 8; nt++) {
                bf[nt][0] = Vs[(ks + t) * 72 + nt * 8 + g];
                bf[nt][1] = Vs[(ks + t + 4) * 72 + nt * 8 + g];
            }
#pragma unroll
            for (int mt = 0; mt < 2; mt++)
#pragma unroll
                for (int nt = 0; nt < 8; nt++)
                    mma8(o[mt][nt], af[mt], bf[nt]);
        }
    }

    const int b = bh >> 2, hd = bh & 3;
#pragma unroll
    for (int mt = 0; mt < 2; mt++)
#pragma unroll
    for (int h = 0; h < 2; h++) {
        const int si = mt * 2 + h;
        float l = l_s[si];
        l += __shfl_xor_sync(0xffffffffu, l, 1);
        l += __shfl_xor_sync(0xffffffffu, l, 2);
        float inv = 1.f / l;
        int n = qt * 128 + mq + mt * 16 + g + h * 8;
        size_t base = ((size_t)(dir * 8192 + b * NN + n)) * NE + hd * ND;
#pragma unroll
        for (int nt = 0; nt < 8; nt++) {
            float2 w;
            w.x = rtf(o[mt][nt][2 * h] * inv);
            w.y = rtf(o[mt][nt][2 * h + 1] * inv);
            *(float2*)&g_am[base + nt * 8 + 2 * t] = w;
        }
    }
}

// ---------------- LayerNorm(512) + exact GELU, in-place, tf32-rounded out ---
__global__ void __launch_bounds__(128) ln_gelu_kernel(
    const float* __restrict__ gvec, const float* __restrict__ bvec)
{
    float* p = g_h1 + (size_t)blockIdx.x * NE2;
    int t = threadIdx.x;
    float4 v = ((const float4*)p)[t];
    float s = v.x + v.y + v.z + v.w;
    float q = v.x * v.x + v.y * v.y + v.z * v.z + v.w * v.w;
#pragma unroll
    for (int off = 16; off > 0; off >>= 1) {
        s += __shfl_xor_sync(0xffffffffu, s, off);
        q += __shfl_xor_sync(0xffffffffu, q, off);
    }
    __shared__ float rs_[4], rq_[4];
    if ((t & 31) == 0) { rs_[t >> 5] = s; rq_[t >> 5] = q; }
    __syncthreads();
    s = rs_[0] + rs_[1] + rs_[2] + rs_[3];
    q = rq_[0] + rq_[1] + rq_[2] + rq_[3];
    float mean = s * (1.f / 512.f);
    float var = q * (1.f / 512.f) - mean * mean;
    float r = rsqrtf(var + 1e-5f);
    float4 gv = ((const float4*)gvec)[t];
    float4 bv = ((const float4*)bvec)[t];
    float xn;
    xn = (v.x - mean) * r * gv.x + bv.x; v.x = rtf(0.5f * xn * (1.f + erff(xn * 0.70710678118654752f)));
    xn = (v.y - mean) * r * gv.y + bv.y; v.y = rtf(0.5f * xn * (1.f + erff(xn * 0.70710678118654752f)));
    xn = (v.z - mean) * r * gv.z + bv.z; v.z = rtf(0.5f * xn * (1.f + erff(xn * 0.70710678118654752f)));
    xn = (v.w - mean) * r * gv.w + bv.w; v.w = rtf(0.5f * xn * (1.f + erff(xn * 0.70710678118654752f)));
    ((float4*)p)[t] = v;
}

// ---------------------------------------------------------------------------
extern "C" void kernel_launch(void* const* d_in, const int* in_sizes, int n_in,
                              void* d_out, int out_size)
{
    const float* x0  = (const float*)d_in[0];
    const float* x1  = (const float*)d_in[1];
    const float* Wqk = (const float*)d_in[2];
    const float* bqk = (const float*)d_in[3];
    const float* Wv  = (const float*)d_in[4];
    const float* bv  = (const float*)d_in[5];
    const float* Wo  = (const float*)d_in[6];
    const float* bo  = (const float*)d_in[7];
    const float* W1  = (const float*)d_in[8];
    const float* b1  = (const float*)d_in[9];
    const float* lng = (const float*)d_in[10];
    const float* lnb = (const float*)d_in[11];
    const float* W2  = (const float*)d_in[12];
    const float* b2  = (const float*)d_in[13];
    float* out = (float*)d_out;
    (void)in_sizes; (void)n_in; (void)out_size;

    const int GEMM_SMEM = 107520;   // 3 stages x 8960 words
    const int ATTN_SMEM = 106496;   // 26624 words -> 2 blocks/SM
    cudaFuncSetAttribute(mgemm<0>, cudaFuncAttributeMaxDynamicSharedMemorySize, GEMM_SMEM);
    cudaFuncSetAttribute(mgemm<1>, cudaFuncAttributeMaxDynamicSharedMemorySize, GEMM_SMEM);
    cudaFuncSetAttribute(mgemm<2>, cudaFuncAttributeMaxDynamicSharedMemorySize, GEMM_SMEM);
    cudaFuncSetAttribute(mgemm<3>, cudaFuncAttributeMaxDynamicSharedMemorySize, GEMM_SMEM);
    cudaFuncSetAttribute(attn_mma, cudaFuncAttributeMaxDynamicSharedMemorySize, ATTN_SMEM);

    // 0) pre-round x + weights to tf32
    cvt_pre<<<4672, 256>>>(x0, x1, Wqk, Wv, Wo, W1, W2);
    // 1) fused qk/v projection
    mgemm<0><<<dim3(4, 128), 256, GEMM_SMEM>>>(bqk, bv, x0, x1, nullptr);
    // 2) bidirectional flash attention (no-max softmax, 2 blocks/SM)
    attn_mma<<<dim3(16, 16, 2), 128, ATTN_SMEM>>>();
    // 3) Wo projection -> g_mo
    mgemm<1><<<dim3(2, 128), 256, GEMM_SMEM>>>(bo, nullptr, x0, x1, nullptr);
    // 4) FFN GEMM1 ([x | mo] @ W1) -> g_h1
    mgemm<2><<<dim3(4, 128), 256, GEMM_SMEM>>>(b1, nullptr, x0, x1, nullptr);
    // 5) LayerNorm + GELU (in place, rounded)
    ln_gelu_kernel<<<16384, 128>>>(lng, lnb);
    // 6) FFN GEMM2 + bias + residual -> out
    mgemm<3><<<dim3(2, 128), 256, GEMM_SMEM>>>(b2, nullptr, x0, x1, out);
}

// round 8
// speedup vs baseline: 3.9355x; 1.1252x over previous
#include <cuda_runtime.h>
#include <cstdint>

#define NB 4
#define NN 2048
#define NE 256
#define NH 4
#define ND 64
#define NE2 512
#define NTOK 16384               // 2 * B * N
#define PER (NB*NH*NN*ND)
#define QK_SCALE 0.35355339059327373f   // 64^-0.25

// ---------------- scratch (device globals; no allocation allowed) ----------
__device__ float g_qk[2][PER];            // pre-rounded tf32 values
__device__ float g_v [2][PER];            // pre-rounded
__device__ float g_am[NTOK*NE];           // attention out (pre-rounded)
__device__ float g_mo[NTOK*NE];           // m @ Wo + bo   (pre-rounded)
__device__ float g_h1[NTOK*NE2];          // FFN1 out (raw), then LN+gelu (rounded)
__device__ float g_xtf[NTOK*NE];          // x0|x1 pre-rounded
__device__ float g_wqk[NE*NE], g_wv[NE*NE], g_wo[NE*NE];
__device__ float g_w1[NE2*NE2], g_w2[NE2*NE];

// ---------------- helpers ---------------------------------------------------
__device__ __forceinline__ uint32_t f2tf(float x) {
    uint32_t r; asm("cvt.rna.tf32.f32 %0, %1;" : "=r"(r) : "f"(x)); return r;
}
__device__ __forceinline__ float rtf(float x) { return __uint_as_float(f2tf(x)); }
__device__ __forceinline__ void cpa16(uint32_t s, const void* g) {
    asm volatile("cp.async.cg.shared.global [%0], [%1], 16;" :: "r"(s), "l"(g));
}
__device__ __forceinline__ void cp_commit() { asm volatile("cp.async.commit_group;"); }
template<int N> __device__ __forceinline__ void cp_wait() {
    asm volatile("cp.async.wait_group %0;" :: "n"(N));
}
// NOTE: not volatile — register-only op, lets the compiler interleave with LDS
__device__ __forceinline__ void mma8(float* d, const uint32_t* a, const uint32_t* b) {
    asm("mma.sync.aligned.m16n8k8.row.col.f32.tf32.tf32.f32 "
        "{%0,%1,%2,%3}, {%4,%5,%6,%7}, {%8,%9}, {%0,%1,%2,%3};\n"
        : "+f"(d[0]), "+f"(d[1]), "+f"(d[2]), "+f"(d[3])
        : "r"(a[0]), "r"(a[1]), "r"(a[2]), "r"(a[3]), "r"(b[0]), "r"(b[1]));
}

// ---------------- pre-round x and all weights to tf32 -----------------------
__global__ void cvt_pre(const float* __restrict__ x0, const float* __restrict__ x1,
                        const float* __restrict__ Wqk, const float* __restrict__ Wv,
                        const float* __restrict__ Wo,  const float* __restrict__ W1,
                        const float* __restrict__ W2)
{
    int i = blockIdx.x * 256 + threadIdx.x;    // float4 index, total 1196032
    const float4* s; float4* d; int j;
    if      (i < 524288)  { j = i;           s = (const float4*)x0;  d = (float4*)g_xtf + j; }
    else if (i < 1048576) { j = i - 524288;  s = (const float4*)x1;  d = (float4*)g_xtf + 524288 + j; }
    else if (i < 1064960) { j = i - 1048576; s = (const float4*)Wqk; d = (float4*)g_wqk + j; }
    else if (i < 1081344) { j = i - 1064960; s = (const float4*)Wv;  d = (float4*)g_wv  + j; }
    else if (i < 1097728) { j = i - 1081344; s = (const float4*)Wo;  d = (float4*)g_wo  + j; }
    else if (i < 1163264) { j = i - 1097728; s = (const float4*)W1;  d = (float4*)g_w1  + j; }
    else                  { j = i - 1163264; s = (const float4*)W2;  d = (float4*)g_w2  + j; }
    float4 v = s[j];
    v.x = rtf(v.x); v.y = rtf(v.y); v.z = rtf(v.z); v.w = rtf(v.w);
    *d = v;
}

// ---------------- tf32 mma GEMM, 128x128 block, cp.async 3-stage ------------
// MODE 0: A=g_xtf  [16384,256], B=Wqk|Wv -> g_qk (scaled,rounded)/g_v (rounded)
// MODE 1: A=g_am   [16384,256], B=Wo     -> g_mo (+bo, rounded)
// MODE 2: A=xtf|mo [16384,512], B=W1     -> g_h1 (+b1, raw)
// MODE 3: A=g_h1   [16384,512], B=W2     -> out  (+b2 + residual)
template<int MODE>
__global__ void __launch_bounds__(256, 2) mgemm(
    const float* __restrict__ ba, const float* __restrict__ bb,
    const float* __restrict__ r0, const float* __restrict__ r1,
    float* __restrict__ out)
{
    constexpr int K   = (MODE >= 2) ? 512 : 256;
    constexpr int LDB = (MODE == 2) ? 512 : 256;
    constexpr int LDA = (MODE == 3) ? 512 : 256;
    constexpr int KT  = K / 32;

    extern __shared__ uint32_t sm[];
    const uint32_t smb = (uint32_t)__cvta_generic_to_shared(sm);
    const int tid = threadIdx.x, wid = tid >> 5, lane = tid & 31;
    const int wm = wid & 3, wn = wid >> 2, g = lane >> 2, t = lane & 3;
    const int bx = blockIdx.x, by = blockIdx.y;

    auto copy_tile = [&](int kt, int st) {
        const int k0 = kt * 32;
        const float* Ab;
        if constexpr (MODE == 0)      Ab = g_xtf + k0;
        else if constexpr (MODE == 1) Ab = g_am + k0;
        else if constexpr (MODE == 2) Ab = (k0 < 256) ? (g_xtf + k0) : (g_mo + (k0 - 256));
        else                          Ab = g_h1 + k0;
        Ab += (size_t)by * 128 * LDA;
        const float* Bb;
        if constexpr (MODE == 0)      Bb = (bx < 2) ? (g_wqk + bx * 128) : (g_wv + (bx - 2) * 128);
        else if constexpr (MODE == 1) Bb = g_wo + bx * 128;
        else if constexpr (MODE == 2) Bb = g_w1 + bx * 128;
        else                          Bb = g_w2 + bx * 128;
        Bb += (size_t)k0 * LDB;
        uint32_t sA = smb + (uint32_t)(st * 8960) * 4;
        uint32_t sB = sA + 4608 * 4;
#pragma unroll
        for (int i = 0; i < 4; i++) {
            int ci = i * 256 + tid, row = ci >> 3, cw = (ci & 7) * 4;
            cpa16(sA + (uint32_t)(row * 36 + cw) * 4, Ab + (size_t)row * LDA + cw);
        }
#pragma unroll
        for (int i = 0; i < 4; i++) {
            int ci = i * 256 + tid, row = ci >> 5, cw = (ci & 31) * 4;
            cpa16(sB + (uint32_t)(row * 136 + cw) * 4, Bb + (size_t)row * LDB + cw);
        }
        cp_commit();
    };

    float acc[2][8][4] = {};

    copy_tile(0, 0);
    copy_tile(1, 1);

    for (int kt = 0; kt < KT; kt++) {
        if (kt + 2 < KT) cp_wait<1>(); else cp_wait<0>();
        __syncthreads();
        if (kt + 2 < KT) copy_tile(kt + 2, (kt + 2) % 3);

        const uint32_t* As = sm + (kt % 3) * 8960;
        const uint32_t* Bs = As + 4608;
#pragma unroll
        for (int ks = 0; ks < 32; ks += 8) {
            uint32_t af[2][4], bf[8][2];
#pragma unroll
            for (int mt = 0; mt < 2; mt++) {
                int mr = wm * 32 + mt * 16 + g;
                af[mt][0] = As[mr * 36 + ks + t];
                af[mt][1] = As[(mr + 8) * 36 + ks + t];
                af[mt][2] = As[mr * 36 + ks + t + 4];
                af[mt][3] = As[(mr + 8) * 36 + ks + t + 4];
            }
#pragma unroll
            for (int nt = 0; nt < 8; nt++) {
                int nc = wn * 64 + nt * 8 + g;
                bf[nt][0] = Bs[(ks + t) * 136 + nc];
                bf[nt][1] = Bs[(ks + t + 4) * 136 + nc];
            }
#pragma unroll
            for (int mt = 0; mt < 2; mt++)
#pragma unroll
                for (int nt = 0; nt < 8; nt++)
                    mma8(acc[mt][nt], af[mt], bf[nt]);
        }
    }

    // epilogue
#pragma unroll
    for (int mt = 0; mt < 2; mt++)
#pragma unroll
    for (int h = 0; h < 2; h++) {
        int r = by * 128 + wm * 32 + mt * 16 + g + h * 8;
#pragma unroll
        for (int nt = 0; nt < 8; nt++) {
            int c = bx * 128 + wn * 64 + nt * 8 + 2 * t;
            float v0 = acc[mt][nt][h * 2 + 0];
            float v1 = acc[mt][nt][h * 2 + 1];
            if constexpr (MODE == 0) {
                int src = r >> 13, rl = r & 8191;
                int b = rl >> 11, n = rl & 2047;
                if (c < 256) {
                    float2 b2 = *(const float2*)&ba[c];
                    int hh = c >> 6, d = c & 63;
                    float2 w;
                    w.x = rtf((v0 + b2.x) * QK_SCALE);
                    w.y = rtf((v1 + b2.y) * QK_SCALE);
                    *(float2*)&g_qk[src][(((size_t)(b * NH + hh)) * NN + n) * ND + d] = w;
                } else {
                    int c2 = c - 256;
                    float2 b2 = *(const float2*)&bb[c2];
                    int hh = c2 >> 6, d = c2 & 63;
                    float2 w; w.x = rtf(v0 + b2.x); w.y = rtf(v1 + b2.y);
                    *(float2*)&g_v[src][(((size_t)(b * NH + hh)) * NN + n) * ND + d] = w;
                }
            } else if constexpr (MODE == 1) {
                float2 b2 = *(const float2*)&ba[c];
                float2 w; w.x = rtf(v0 + b2.x); w.y = rtf(v1 + b2.y);
                *(float2*)&g_mo[(size_t)r * NE + c] = w;
            } else if constexpr (MODE == 2) {
                float2 b2 = *(const float2*)&ba[c];
                float2 w; w.x = v0 + b2.x; w.y = v1 + b2.y;
                *(float2*)&g_h1[(size_t)r * NE2 + c] = w;
            } else {
                int src = r >> 13, rl = r & 8191;
                const float* xr = src ? r1 : r0;
                float2 b2 = *(const float2*)&ba[c];
                float2 xv = *(const float2*)&xr[(size_t)rl * NE + c];
                float2 w; w.x = v0 + b2.x + xv.x; w.y = v1 + b2.y + xv.y;
                *(float2*)&out[(size_t)r * NE + c] = w;
            }
        }
    }
}

// ---------------- flash attention: P in registers via kv-permutation --------
// block = 128 threads (4 warps), Q-tile 128 rows, warp tile 32x64, 2-stage KV
// kv axis inside each 8-group permuted by pi(u) = 2u (u<4) else 2(u-4)+1, so
// the S accumulator IS the PV A-fragment: af = {e(c0), e(c2), e(c1), e(c3)}.
// V fragment rows are read permuted the same way (rows ks+2t, ks+2t+1).
// smem words: K 2 x 64x68 = 8704 | V 2 x 64x68 = 8704  (Q staged over K region)
// total 17408 words = 69632 B -> 2 blocks/SM
__global__ void __launch_bounds__(128, 2) attn_mma()
{
    extern __shared__ uint32_t smx[];
    const uint32_t smb = (uint32_t)__cvta_generic_to_shared(smx);

    const int qt = blockIdx.x, bh = blockIdx.y, dir = blockIdx.z;
    const int tid = threadIdx.x, wid = tid >> 5, lane = tid & 31;
    const int g = lane >> 2, t = lane & 3, mq = wid * 32;

    const float* Q  = g_qk[dir]     + (size_t)bh * NN * ND + (size_t)qt * 128 * ND;
    const float* Kp = g_qk[dir ^ 1] + (size_t)bh * NN * ND;
    const float* Vp = g_v [dir ^ 1] + (size_t)bh * NN * ND;

    // stage Q into smem [0, 8704) words (overlays K stages; loads come later)
    {
        int row = tid;
#pragma unroll
        for (int i = 0; i < 16; i++)
            *(float4*)&smx[row * 68 + i * 4] =
                *(const float4*)(Q + (size_t)row * ND + i * 4);
    }
    __syncthreads();

    uint32_t qf[2][8][4];
#pragma unroll
    for (int mt = 0; mt < 2; mt++) {
        int mr = mq + mt * 16 + g;
#pragma unroll
        for (int k8 = 0; k8 < 8; k8++) {
            qf[mt][k8][0] = smx[mr * 68 + k8 * 8 + t];
            qf[mt][k8][1] = smx[(mr + 8) * 68 + k8 * 8 + t];
            qf[mt][k8][2] = smx[mr * 68 + k8 * 8 + t + 4];
            qf[mt][k8][3] = smx[(mr + 8) * 68 + k8 * 8 + t + 4];
        }
    }
    __syncthreads();

    auto load_kv = [&](int j, int st) {
        uint32_t sK = smb + (uint32_t)(st * 4352) * 4;
        uint32_t sV = smb + (uint32_t)(8704 + st * 4352) * 4;
        const float* kb = Kp + (size_t)j * 64 * ND;
        const float* vb = Vp + (size_t)j * 64 * ND;
#pragma unroll
        for (int i = 0; i < 8; i++) {
            int ci = i * 128 + tid, row = ci >> 4, cw = (ci & 15) * 4;
            cpa16(sK + (uint32_t)(row * 68 + cw) * 4, kb + row * 64 + cw);
            cpa16(sV + (uint32_t)(row * 68 + cw) * 4, vb + row * 64 + cw);
        }
        cp_commit();
    };

    float o[2][8][4] = {};
    float l_s[4] = {};

    load_kv(0, 0);

    for (int j = 0; j < 32; j++) {
        cp_wait<0>();
        __syncthreads();
        if (j + 1 < 32) load_kv(j + 1, (j + 1) & 1);

        const uint32_t* Ks = smx + (j & 1) * 4352;
        const uint32_t* Vs = smx + 8704 + (j & 1) * 4352;

        // S = Q K^T  (32 x 64 per warp)
        float s[2][8][4] = {};
#pragma unroll
        for (int ks = 0; ks < 64; ks += 8) {
            uint32_t bf[8][2];
#pragma unroll
            for (int nt = 0; nt < 8; nt++) {
                bf[nt][0] = Ks[(nt * 8 + g) * 68 + ks + t];
                bf[nt][1] = Ks[(nt * 8 + g) * 68 + ks + t + 4];
            }
#pragma unroll
            for (int mt = 0; mt < 2; mt++)
#pragma unroll
                for (int nt = 0; nt < 8; nt++)
                    mma8(s[mt][nt], qf[mt][ks >> 3], bf[nt]);
        }

        // no-max softmax: exp in registers; repack acc {c0,c1,c2,c3} ->
        // A-frag {c0,c2,c1,c3} (kv permutation), accumulate l per row half
#pragma unroll
        for (int mt = 0; mt < 2; mt++)
#pragma unroll
        for (int nt = 0; nt < 8; nt++) {
            uint32_t e0 = f2tf(__expf(s[mt][nt][0]));
            uint32_t e1 = f2tf(__expf(s[mt][nt][1]));
            uint32_t e2 = f2tf(__expf(s[mt][nt][2]));
            uint32_t e3 = f2tf(__expf(s[mt][nt][3]));
            l_s[mt * 2 + 0] += __uint_as_float(e0) + __uint_as_float(e1);
            l_s[mt * 2 + 1] += __uint_as_float(e2) + __uint_as_float(e3);
            uint32_t* su = (uint32_t*)s[mt][nt];
            su[0] = e0; su[1] = e2; su[2] = e1; su[3] = e3;
        }

        // O += P' V'   (kv-permuted; V rows read as ks+2t, ks+2t+1)
#pragma unroll
        for (int ks = 0; ks < 64; ks += 8) {
            uint32_t bf[8][2];
#pragma unroll
            for (int nt = 0; nt < 8; nt++) {
                bf[nt][0] = Vs[(ks + 2 * t) * 68 + nt * 8 + g];
                bf[nt][1] = Vs[(ks + 2 * t + 1) * 68 + nt * 8 + g];
            }
#pragma unroll
            for (int mt = 0; mt < 2; mt++)
#pragma unroll
                for (int nt = 0; nt < 8; nt++)
                    mma8(o[mt][nt], (const uint32_t*)s[mt][ks >> 3], bf[nt]);
        }
    }

    const int b = bh >> 2, hd = bh & 3;
#pragma unroll
    for (int mt = 0; mt < 2; mt++)
#pragma unroll
    for (int h = 0; h < 2; h++) {
        const int si = mt * 2 + h;
        float l = l_s[si];
        l += __shfl_xor_sync(0xffffffffu, l, 1);
        l += __shfl_xor_sync(0xffffffffu, l, 2);
        float inv = 1.f / l;
        int n = qt * 128 + mq + mt * 16 + g + h * 8;
        size_t base = ((size_t)(dir * 8192 + b * NN + n)) * NE + hd * ND;
#pragma unroll
        for (int nt = 0; nt < 8; nt++) {
            float2 w;
            w.x = rtf(o[mt][nt][2 * h] * inv);
            w.y = rtf(o[mt][nt][2 * h + 1] * inv);
            *(float2*)&g_am[base + nt * 8 + 2 * t] = w;
        }
    }
}

// ---------------- LayerNorm(512) + exact GELU, in-place, tf32-rounded out ---
__global__ void __launch_bounds__(128) ln_gelu_kernel(
    const float* __restrict__ gvec, const float* __restrict__ bvec)
{
    float* p = g_h1 + (size_t)blockIdx.x * NE2;
    int t = threadIdx.x;
    float4 v = ((const float4*)p)[t];
    float s = v.x + v.y + v.z + v.w;
    float q = v.x * v.x + v.y * v.y + v.z * v.z + v.w * v.w;
#pragma unroll
    for (int off = 16; off > 0; off >>= 1) {
        s += __shfl_xor_sync(0xffffffffu, s, off);
        q += __shfl_xor_sync(0xffffffffu, q, off);
    }
    __shared__ float rs_[4], rq_[4];
    if ((t & 31) == 0) { rs_[t >> 5] = s; rq_[t >> 5] = q; }
    __syncthreads();
    s = rs_[0] + rs_[1] + rs_[2] + rs_[3];
    q = rq_[0] + rq_[1] + rq_[2] + rq_[3];
    float mean = s * (1.f / 512.f);
    float var = q * (1.f / 512.f) - mean * mean;
    float r = rsqrtf(var + 1e-5f);
    float4 gv = ((const float4*)gvec)[t];
    float4 bv = ((const float4*)bvec)[t];
    float xn;
    xn = (v.x - mean) * r * gv.x + bv.x; v.x = rtf(0.5f * xn * (1.f + erff(xn * 0.70710678118654752f)));
    xn = (v.y - mean) * r * gv.y + bv.y; v.y = rtf(0.5f * xn * (1.f + erff(xn * 0.70710678118654752f)));
    xn = (v.z - mean) * r * gv.z + bv.z; v.z = rtf(0.5f * xn * (1.f + erff(xn * 0.70710678118654752f)));
    xn = (v.w - mean) * r * gv.w + bv.w; v.w = rtf(0.5f * xn * (1.f + erff(xn * 0.70710678118654752f)));
    ((float4*)p)[t] = v;
}

// ---------------------------------------------------------------------------
extern "C" void kernel_launch(void* const* d_in, const int* in_sizes, int n_in,
                              void* d_out, int out_size)
{
    const float* x0  = (const float*)d_in[0];
    const float* x1  = (const float*)d_in[1];
    const float* Wqk = (const float*)d_in[2];
    const float* bqk = (const float*)d_in[3];
    const float* Wv  = (const float*)d_in[4];
    const float* bv  = (const float*)d_in[5];
    const float* Wo  = (const float*)d_in[6];
    const float* bo  = (const float*)d_in[7];
    const float* W1  = (const float*)d_in[8];
    const float* b1  = (const float*)d_in[9];
    const float* lng = (const float*)d_in[10];
    const float* lnb = (const float*)d_in[11];
    const float* W2  = (const float*)d_in[12];
    const float* b2  = (const float*)d_in[13];
    float* out = (float*)d_out;
    (void)in_sizes; (void)n_in; (void)out_size;

    const int GEMM_SMEM = 107520;   // 3 stages x 8960 words
    const int ATTN_SMEM = 69632;    // 17408 words -> 2 blocks/SM
    cudaFuncSetAttribute(mgemm<0>, cudaFuncAttributeMaxDynamicSharedMemorySize, GEMM_SMEM);
    cudaFuncSetAttribute(mgemm<1>, cudaFuncAttributeMaxDynamicSharedMemorySize, GEMM_SMEM);
    cudaFuncSetAttribute(mgemm<2>, cudaFuncAttributeMaxDynamicSharedMemorySize, GEMM_SMEM);
    cudaFuncSetAttribute(mgemm<3>, cudaFuncAttributeMaxDynamicSharedMemorySize, GEMM_SMEM);
    cudaFuncSetAttribute(attn_mma, cudaFuncAttributeMaxDynamicSharedMemorySize, ATTN_SMEM);

    // 0) pre-round x + weights to tf32
    cvt_pre<<<4672, 256>>>(x0, x1, Wqk, Wv, Wo, W1, W2);
    // 1) fused qk/v projection
    mgemm<0><<<dim3(4, 128), 256, GEMM_SMEM>>>(bqk, bv, x0, x1, nullptr);
    // 2) bidirectional flash attention (P-in-registers, 2 blocks/SM)
    attn_mma<<<dim3(16, 16, 2), 128, ATTN_SMEM>>>();
    // 3) Wo projection -> g_mo
    mgemm<1><<<dim3(2, 128), 256, GEMM_SMEM>>>(bo, nullptr, x0, x1, nullptr);
    // 4) FFN GEMM1 ([x | mo] @ W1) -> g_h1
    mgemm<2><<<dim3(4, 128), 256, GEMM_SMEM>>>(b1, nullptr, x0, x1, nullptr);
    // 5) LayerNorm + GELU (in place, rounded)
    ln_gelu_kernel<<<16384, 128>>>(lng, lnb);
    // 6) FFN GEMM2 + bias + residual -> out
    mgemm<3><<<dim3(2, 128), 256, GEMM_SMEM>>>(b2, nullptr, x0, x1, out);
}